// round 3
// baseline (speedup 1.0000x reference)
#include <cuda_runtime.h>
#include <cstdint>

#define B      8192
#define DDIM   256
#define SPLIT  8
#define BM     128
#define BN     64
#define BSTRIDE 68                      // padded Bs row (floats)
#define COLS_PER_BLOCK (B / SPLIT)      // 1024
#define NTILES (COLS_PER_BLOCK / BN)    // 16
#define INV_T  10.0f

// ---------------- scratch (device globals: no allocation allowed) ----------
__device__ float g_sq[B];
__device__ int   g_lab[B];
__device__ int   g_jsel[B];
__device__ int   g_valid[B];
__device__ float g_num[B];
__device__ float g_pm[SPLIT][B];
__device__ float g_ps[SPLIT][B];
__device__ int   g_lab64;               // 1 if labels are int64, else int32

// ------------- dtype detect: odd 32-bit words all zero <=> int64 ----------
__global__ void detect_kernel(const unsigned* __restrict__ words) {
    __shared__ unsigned sOr[256];
    unsigned v = 0;
    // words 0..B-1 are in-bounds whether labels are int32 (B words) or int64 (2B words)
    for (int k = threadIdx.x; k < B / 2; k += 256) v |= words[2 * k + 1];
    sOr[threadIdx.x] = v;
    __syncthreads();
    for (int off = 128; off; off >>= 1) {
        if (threadIdx.x < off) sOr[threadIdx.x] |= sOr[threadIdx.x + off];
        __syncthreads();
    }
    if (threadIdx.x == 0) g_lab64 = (sOr[0] == 0u) ? 1 : 0;
}

// ---------------- prep: row squared norms + label narrowing ----------------
__global__ void prep_kernel(const float* __restrict__ emb,
                            const void* __restrict__ labels) {
    int gtid = blockIdx.x * blockDim.x + threadIdx.x;
    int warp = gtid >> 5;
    int lane = threadIdx.x & 31;
    if (warp < B) {
        const float* row = emb + (size_t)warp * DDIM;
        float s = 0.f;
#pragma unroll
        for (int k = 0; k < DDIM; k += 32) {
            float v = row[k + lane];
            s = fmaf(v, v, s);
        }
#pragma unroll
        for (int off = 16; off; off >>= 1)
            s += __shfl_xor_sync(0xffffffffu, s, off);
        if (lane == 0) g_sq[warp] = s;
    }
    if (gtid < B) {
        int lab = g_lab64 ? (int)((const long long*)labels)[gtid]
                          : ((const int*)labels)[gtid];
        g_lab[gtid] = lab;
    }
}

// ------- threefry2x32, JAX partitionable mode, key=(0,42) ------------------
// element p of a 2^26 draw: counter pair (hi32(p), lo32(p)) = (0, p),
// 32-bit output = out0 ^ out1.
__device__ __forceinline__ unsigned rotl32(unsigned x, int r) {
    return __funnelshift_l(x, x, r);
}

__device__ __forceinline__ unsigned threefry_bits(unsigned idx) {
    const unsigned ks0 = 0u, ks1 = 42u, ks2 = 0u ^ 42u ^ 0x1BD11BDAu;
    unsigned x0 = 0u + ks0, x1 = idx + ks1;
#define TFR(r) { x0 += x1; x1 = rotl32(x1, r); x1 ^= x0; }
    TFR(13) TFR(15) TFR(26) TFR(6)   x0 += ks1; x1 += ks2 + 1u;
    TFR(17) TFR(29) TFR(16) TFR(24)  x0 += ks2; x1 += ks0 + 2u;
    TFR(13) TFR(15) TFR(26) TFR(6)   x0 += ks0; x1 += ks1 + 3u;
    TFR(17) TFR(29) TFR(16) TFR(24)  x0 += ks1; x1 += ks2 + 4u;
    TFR(13) TFR(15) TFR(26) TFR(6)   x0 += ks2; x1 += ks0 + 5u;
#undef TFR
    return x0 ^ x1;
}

// ---------------- positive selection: gumbel-argmax == bits-argmax ---------
__global__ void select_kernel() {
    int i = blockIdx.x;
    int labi = g_lab[i];
    unsigned bv = 0; int bj = -1; int cnt = 0;
    for (int j = threadIdx.x; j < B; j += blockDim.x) {
        if (g_lab[j] == labi && j != i) {
            cnt++;
            unsigned v = threefry_bits((unsigned)(i * B + j)) >> 9;
            if (bj < 0 || v > bv) { bv = v; bj = j; }   // j ascending per thread
        }
    }
    const unsigned full = 0xffffffffu;
#pragma unroll
    for (int off = 16; off; off >>= 1) {
        unsigned ov = __shfl_down_sync(full, bv, off);
        int oj = __shfl_down_sync(full, bj, off);
        int oc = __shfl_down_sync(full, cnt, off);
        cnt += oc;
        if (oj >= 0 && (bj < 0 || ov > bv || (ov == bv && oj < bj))) { bv = ov; bj = oj; }
    }
    __shared__ unsigned sv[4]; __shared__ int sj[4]; __shared__ int sc[4];
    int w = threadIdx.x >> 5;
    if ((threadIdx.x & 31) == 0) { sv[w] = bv; sj[w] = bj; sc[w] = cnt; }
    __syncthreads();
    if (threadIdx.x == 0) {
        bv = sv[0]; bj = sj[0]; cnt = sc[0];
        for (int w2 = 1; w2 < 4; ++w2) {
            cnt += sc[w2];
            if (sj[w2] >= 0 && (bj < 0 || sv[w2] > bv || (sv[w2] == bv && sj[w2] < bj))) {
                bv = sv[w2]; bj = sj[w2];
            }
        }
        g_jsel[i]  = bj;
        g_valid[i] = (cnt > 0) && ((B - (cnt + 1)) > 0);
    }
}

// -------- fused Gram + masked online logsumexp + numerator pick ------------
__global__ void __launch_bounds__(256, 1)
main_kernel(const float* __restrict__ emb) {
    extern __shared__ float smf[];
    float* As  = smf;                       // [256][128] transposed A tile
    float* Bs  = As + DDIM * BM;            // [256][68]  transposed B tile
    float* sSq = Bs + DDIM * BSTRIDE;       // [1024]
    int*   sLab = (int*)(sSq + COLS_PER_BLOCK);

    const int tid = threadIdx.x;
    const int tx = tid & 15, ty = tid >> 4;
    const int split   = blockIdx.x;
    const int rowBase = blockIdx.y * BM;
    const int colBase = split * COLS_PER_BLOCK;

    // column metadata for this block's 1024-column slice
#pragma unroll
    for (int it = 0; it < COLS_PER_BLOCK / 256; ++it) {
        int c = tid + it * 256;
        sLab[c] = g_lab[colBase + c];
        sSq[c]  = g_sq[colBase + c];
    }
    // stage A tile (128 rows x 256 k), transposed As[k][m]
#pragma unroll
    for (int it = 0; it < (BM * DDIM / 4) / 256; ++it) {   // 32 iters
        int f  = tid + it * 256;
        int m  = f & (BM - 1);
        int k4 = f >> 7;
        float4 v = *reinterpret_cast<const float4*>(
            emb + (size_t)(rowBase + m) * DDIM + k4 * 4);
        As[(k4 * 4 + 0) * BM + m] = v.x;
        As[(k4 * 4 + 1) * BM + m] = v.y;
        As[(k4 * 4 + 2) * BM + m] = v.z;
        As[(k4 * 4 + 3) * BM + m] = v.w;
    }

    float sqi[8]; int labi[8]; int jsel[8];
#pragma unroll
    for (int rr = 0; rr < 8; ++rr) {
        int r = rowBase + ty * 8 + rr;
        sqi[rr]  = g_sq[r];
        labi[rr] = g_lab[r];
        jsel[rr] = g_jsel[r];
    }
    float m_[8], s_[8];
#pragma unroll
    for (int rr = 0; rr < 8; ++rr) { m_[rr] = -1e30f; s_[rr] = 0.f; }

    for (int ct = 0; ct < NTILES; ++ct) {
        __syncthreads();   // previous tile's Bs readers done
        // stage B tile (64 cols x 256 k), transposed Bs[k][c]
#pragma unroll
        for (int it = 0; it < (BN * DDIM / 4) / 256; ++it) {   // 16 iters
            int f  = tid + it * 256;
            int c  = f & (BN - 1);
            int k4 = f >> 6;
            float4 v = *reinterpret_cast<const float4*>(
                emb + (size_t)(colBase + ct * BN + c) * DDIM + k4 * 4);
            Bs[(k4 * 4 + 0) * BSTRIDE + c] = v.x;
            Bs[(k4 * 4 + 1) * BSTRIDE + c] = v.y;
            Bs[(k4 * 4 + 2) * BSTRIDE + c] = v.z;
            Bs[(k4 * 4 + 3) * BSTRIDE + c] = v.w;
        }
        __syncthreads();

        float acc[8][4];
#pragma unroll
        for (int rr = 0; rr < 8; ++rr)
#pragma unroll
            for (int cc = 0; cc < 4; ++cc) acc[rr][cc] = 0.f;

#pragma unroll 8
        for (int k = 0; k < DDIM; ++k) {
            float4 a0 = *reinterpret_cast<const float4*>(&As[k * BM + ty * 8]);
            float4 a1 = *reinterpret_cast<const float4*>(&As[k * BM + ty * 8 + 4]);
            float4 b  = *reinterpret_cast<const float4*>(&Bs[k * BSTRIDE + tx * 4]);
            float ar[8] = {a0.x, a0.y, a0.z, a0.w, a1.x, a1.y, a1.z, a1.w};
            float br[4] = {b.x, b.y, b.z, b.w};
#pragma unroll
            for (int rr = 0; rr < 8; ++rr)
#pragma unroll
                for (int cc = 0; cc < 4; ++cc)
                    acc[rr][cc] = fmaf(ar[rr], br[cc], acc[rr][cc]);
        }

        // epilogue: fold tile into running logsumexp / numerator
#pragma unroll
        for (int cc = 0; cc < 4; ++cc) {
            int cl   = ct * BN + tx * 4 + cc;
            int c    = colBase + cl;
            int labc = sLab[cl];
            float sqc = sSq[cl];
#pragma unroll
            for (int rr = 0; rr < 8; ++rr) {
                float t   = sqi[rr] + sqc;
                float d2  = fmaxf(fmaf(-2.0f, acc[rr][cc], t), 0.0f);
                float sim = -INV_T * d2;
                if (labc != labi[rr]) {                       // negative
                    float d = sim - m_[rr];
                    if (d > 0.0f) {
                        s_[rr] = fmaf(s_[rr], __expf(-d), 1.0f);
                        m_[rr] = sim;
                    } else if (d > -87.0f) {
                        s_[rr] += __expf(d);
                    }
                } else if (c == jsel[rr]) {                   // selected positive
                    g_num[rowBase + ty * 8 + rr] = sim;
                }
            }
        }
    }

    // reduce (m,s) across the 16 tx lanes (contiguous within half-warp)
#pragma unroll
    for (int off = 1; off < 16; off <<= 1) {
#pragma unroll
        for (int rr = 0; rr < 8; ++rr) {
            float mo = __shfl_xor_sync(0xffffffffu, m_[rr], off);
            float so = __shfl_xor_sync(0xffffffffu, s_[rr], off);
            float mn = fmaxf(m_[rr], mo);
            s_[rr] = s_[rr] * __expf(m_[rr] - mn) + so * __expf(mo - mn);
            m_[rr] = mn;
        }
    }
    if (tx == 0) {
#pragma unroll
        for (int rr = 0; rr < 8; ++rr) {
            int r = rowBase + ty * 8 + rr;
            g_pm[split][r] = m_[rr];
            g_ps[split][r] = s_[rr];
        }
    }
}

// ---------------- finalize: combine splits, masked mean --------------------
__global__ void finalize_kernel(float* __restrict__ out) {
    __shared__ double ssum[256];
    __shared__ int    scnt[256];
    int tid = threadIdx.x;
    double acc = 0.0; int cnt = 0;
    for (int r = tid; r < B; r += 256) {
        if (g_valid[r]) {
            float m = -1e30f;
#pragma unroll
            for (int k = 0; k < SPLIT; ++k) m = fmaxf(m, g_pm[k][r]);
            float s = 0.f;
#pragma unroll
            for (int k = 0; k < SPLIT; ++k)
                s += g_ps[k][r] * __expf(g_pm[k][r] - m);
            float denom = m + __logf(s);
            acc += (double)(denom - g_num[r]);   // per_row = -(num - denom)
            cnt++;
        }
    }
    ssum[tid] = acc; scnt[tid] = cnt;
    __syncthreads();
    for (int off = 128; off; off >>= 1) {
        if (tid < off) { ssum[tid] += ssum[tid + off]; scnt[tid] += scnt[tid + off]; }
        __syncthreads();
    }
    if (tid == 0)
        out[0] = (scnt[0] > 0) ? (float)(ssum[0] / (double)scnt[0]) : 0.0f;
}

// ---------------------------------------------------------------------------
extern "C" void kernel_launch(void* const* d_in, const int* in_sizes, int n_in,
                              void* d_out, int out_size) {
    const float* emb    = (const float*)d_in[0];
    const void*  labels = d_in[1];

    const int smem_bytes =
        (DDIM * BM + DDIM * BSTRIDE + COLS_PER_BLOCK) * (int)sizeof(float) +
        COLS_PER_BLOCK * (int)sizeof(int);   // 208896 B

    cudaFuncSetAttribute(main_kernel,
                         cudaFuncAttributeMaxDynamicSharedMemorySize, smem_bytes);

    detect_kernel<<<1, 256>>>((const unsigned*)labels);
    prep_kernel<<<(B * 32) / 256, 256>>>(emb, labels);
    select_kernel<<<B, 128>>>();
    main_kernel<<<dim3(SPLIT, B / BM), 256, smem_bytes>>>(emb);
    finalize_kernel<<<1, 256>>>((float*)d_out);
}

// round 7
// speedup vs baseline: 3.3626x; 3.3626x over previous
#include <cuda_runtime.h>
#include <cuda_bf16.h>
#include <cstdint>

#define B     8192
#define DDIM  256
#define BM    64
#define BN    128
#define NT    (B / BN)        // 64 col tiles
#define KSTEPS 32             // K = 512 = [hi(256) | lo(256)]
// SMEM layout (bytes)
#define SM_A    0             // 64 rows * 1024 B  = 65536
#define SM_B0   65536         // 128 * 512 B      = 65536
#define SM_B1   131072
#define SM_META 196608        // 2 * (128 f32 base + 128 i32 lab) = 2048
#define SM_RED  198656        // 4 * 64 * float2 = 2048
#define SM_TOTAL 200704

// ---------------- scratch ----------------
__device__ uint4 g_ehi4[B * DDIM / 8];
__device__ uint4 g_elo4[B * DDIM / 8];
__device__ float g_basec[B];     // -10 * ||x||^2
__device__ int   g_lab[B];
__device__ int   g_jsel[B];
__device__ int   g_valid[B];
__device__ float g_num[B];
__device__ float g_den[B];
__device__ int   g_lab64;
__device__ int   g_off[256];
__device__ int   g_cnt[256];
__device__ int   g_cls[B];

// ---------------- helpers ----------------
__device__ __forceinline__ uint32_t smem_u32(const void* p) {
    uint32_t a;
    asm("{ .reg .u64 t; cvta.to.shared.u64 t, %1; cvt.u32.u64 %0, t; }" : "=r"(a) : "l"(p));
    return a;
}
__device__ __forceinline__ void cpa16(uint32_t dst, const void* src) {
    asm volatile("cp.async.cg.shared.global [%0], [%1], 16;" :: "r"(dst), "l"(src));
}
__device__ __forceinline__ void cp_commit() { asm volatile("cp.async.commit_group;" ::: "memory"); }
template<int N> __device__ __forceinline__ void cp_wait() {
    asm volatile("cp.async.wait_group %0;" :: "n"(N) : "memory");
}
__device__ __forceinline__ void ldsm4(uint32_t& r0, uint32_t& r1, uint32_t& r2, uint32_t& r3, uint32_t a) {
    asm volatile("ldmatrix.sync.aligned.m8n8.x4.shared.b16 {%0,%1,%2,%3}, [%4];"
                 : "=r"(r0), "=r"(r1), "=r"(r2), "=r"(r3) : "r"(a));
}
__device__ __forceinline__ void mma16816(float* d, const uint32_t* a, const uint32_t* b) {
    asm volatile("mma.sync.aligned.m16n8k16.row.col.f32.bf16.bf16.f32 "
                 "{%0,%1,%2,%3}, {%4,%5,%6,%7}, {%8,%9}, {%0,%1,%2,%3};"
                 : "+f"(d[0]), "+f"(d[1]), "+f"(d[2]), "+f"(d[3])
                 : "r"(a[0]), "r"(a[1]), "r"(a[2]), "r"(a[3]), "r"(b[0]), "r"(b[1]));
}

// ------------- dtype detect: odd 32-bit words all zero <=> int64 ----------
__global__ void detect_kernel(const unsigned* __restrict__ words) {
    __shared__ unsigned sOr[256];
    unsigned v = 0;
    for (int k = threadIdx.x; k < B / 2; k += 256) v |= words[2 * k + 1];
    sOr[threadIdx.x] = v;
    __syncthreads();
    for (int off = 128; off; off >>= 1) {
        if (threadIdx.x < off) sOr[threadIdx.x] |= sOr[threadIdx.x + off];
        __syncthreads();
    }
    if (threadIdx.x == 0) g_lab64 = (sOr[0] == 0u) ? 1 : 0;
}

// ------------- prep: norms, labels, bf16 hi/lo split -----------------------
__global__ void prep_kernel(const float* __restrict__ emb,
                            const void* __restrict__ labels) {
    int warp = (blockIdx.x * blockDim.x + threadIdx.x) >> 5;
    int lane = threadIdx.x & 31;
    if (warp >= B) return;
    const float* row = emb + (size_t)warp * DDIM;
    float x[8];
    {
        float4 a = *reinterpret_cast<const float4*>(row + lane * 8);
        float4 b = *reinterpret_cast<const float4*>(row + lane * 8 + 4);
        x[0]=a.x; x[1]=a.y; x[2]=a.z; x[3]=a.w; x[4]=b.x; x[5]=b.y; x[6]=b.z; x[7]=b.w;
    }
    float s = 0.f;
    unsigned hu[4], lu[4];
#pragma unroll
    for (int e = 0; e < 8; e += 2) {
        __nv_bfloat16 h0 = __float2bfloat16(x[e]);
        __nv_bfloat16 h1 = __float2bfloat16(x[e + 1]);
        __nv_bfloat16 l0 = __float2bfloat16(x[e] - __bfloat162float(h0));
        __nv_bfloat16 l1 = __float2bfloat16(x[e + 1] - __bfloat162float(h1));
        hu[e >> 1] = (unsigned)__bfloat16_as_ushort(h0) | ((unsigned)__bfloat16_as_ushort(h1) << 16);
        lu[e >> 1] = (unsigned)__bfloat16_as_ushort(l0) | ((unsigned)__bfloat16_as_ushort(l1) << 16);
        s = fmaf(x[e], x[e], s);
        s = fmaf(x[e + 1], x[e + 1], s);
    }
    g_ehi4[warp * 32 + lane] = make_uint4(hu[0], hu[1], hu[2], hu[3]);
    g_elo4[warp * 32 + lane] = make_uint4(lu[0], lu[1], lu[2], lu[3]);
#pragma unroll
    for (int off = 16; off; off >>= 1) s += __shfl_xor_sync(0xffffffffu, s, off);
    if (lane == 0) {
        g_basec[warp] = -10.0f * s;
        int lab = g_lab64 ? (int)((const long long*)labels)[warp]
                          : ((const int*)labels)[warp];
        g_lab[warp] = lab;
    }
}

// ------------- class bucketing -------------
__global__ void sortclass_kernel() {
    __shared__ int h[256], off[256];
    int t = threadIdx.x;
    h[t] = 0;
    __syncthreads();
    for (int i = t; i < B; i += 256) atomicAdd(&h[g_lab[i] & 255], 1);
    __syncthreads();
    if (t == 0) {
        int acc = 0;
        for (int c = 0; c < 256; ++c) { off[c] = acc; acc += h[c]; }
    }
    __syncthreads();
    g_cnt[t] = h[t];
    g_off[t] = off[t];
    h[t] = off[t];
    __syncthreads();
    for (int i = t; i < B; i += 256) {
        int pos = atomicAdd(&h[g_lab[i] & 255], 1);
        g_cls[pos] = i;
    }
}

// ------- threefry2x32, JAX partitionable mode, key=(0,42) ------------------
__device__ __forceinline__ unsigned rotl32(unsigned x, int r) {
    return __funnelshift_l(x, x, r);
}
__device__ __forceinline__ unsigned threefry_bits(unsigned idx) {
    const unsigned ks0 = 0u, ks1 = 42u, ks2 = 0u ^ 42u ^ 0x1BD11BDAu;
    unsigned x0 = 0u + ks0, x1 = idx + ks1;
#define TFR(r) { x0 += x1; x1 = rotl32(x1, r); x1 ^= x0; }
    TFR(13) TFR(15) TFR(26) TFR(6)   x0 += ks1; x1 += ks2 + 1u;
    TFR(17) TFR(29) TFR(16) TFR(24)  x0 += ks2; x1 += ks0 + 2u;
    TFR(13) TFR(15) TFR(26) TFR(6)   x0 += ks0; x1 += ks1 + 3u;
    TFR(17) TFR(29) TFR(16) TFR(24)  x0 += ks1; x1 += ks2 + 4u;
    TFR(13) TFR(15) TFR(26) TFR(6)   x0 += ks2; x1 += ks0 + 5u;
#undef TFR
    return x0 ^ x1;
}

// ------------- positive selection: warp per row over its class list --------
__global__ void select_kernel() {
    int warp = (blockIdx.x * blockDim.x + threadIdx.x) >> 5;
    int lane = threadIdx.x & 31;
    if (warp >= B) return;
    int i = warp;
    int lab = g_lab[i] & 255;
    int base = g_off[lab], n = g_cnt[lab];
    unsigned bv = 0; int bj = -1;
    for (int t = lane; t < n; t += 32) {
        int j = g_cls[base + t];
        if (j == i) continue;
        unsigned v = threefry_bits((unsigned)(i * B + j)) >> 9;
        if (bj < 0 || v > bv || (v == bv && j < bj)) { bv = v; bj = j; }
    }
    const unsigned full = 0xffffffffu;
#pragma unroll
    for (int off = 16; off; off >>= 1) {
        unsigned ov = __shfl_down_sync(full, bv, off);
        int oj = __shfl_down_sync(full, bj, off);
        if (oj >= 0 && (bj < 0 || ov > bv || (ov == bv && oj < bj))) { bv = ov; bj = oj; }
    }
    if (lane == 0) {
        g_jsel[i] = bj;
        g_valid[i] = (n - 1 > 0) && (B - n > 0);
    }
}

// ------------- main: HMMA bf16-split Gram + fused logsumexp ----------------
__device__ __forceinline__ void stage_tile(int ct, int p, int tid, uint32_t smb) {
    int c0 = ct * BN;
    uint32_t bbuf = smb + SM_B0 + (uint32_t)p * 65536u;
#pragma unroll
    for (int it = 0; it < 16; ++it) {
        int f = tid + it * 256;
        int n = f >> 5, v = f & 31;
        uint32_t off = (uint32_t)(n * 512 + v * 16);
        off ^= (uint32_t)(n & 7) << 4;
        cpa16(bbuf + off, g_ehi4 + (size_t)(c0 + n) * 32 + v);
    }
    uint32_t mbuf = smb + SM_META + (uint32_t)p * 1024u;
    if (tid < 32)      cpa16(mbuf + tid * 16, (const char*)g_basec + (size_t)c0 * 4 + tid * 16);
    else if (tid < 64) cpa16(mbuf + 512 + (tid - 32) * 16, (const char*)g_lab + (size_t)c0 * 4 + (tid - 32) * 16);
    cp_commit();
}

__global__ void __launch_bounds__(256, 1)
main_kernel() {
    extern __shared__ char smem[];
    const uint32_t smb = smem_u32(smem);
    const int tid = threadIdx.x;
    const int lane = tid & 31, wid = tid >> 5;
    const int wm = wid >> 2, wn = wid & 3;
    const int rowBase = blockIdx.x * BM;

    // prologue: kick off tile 0, stage A while it flies
    stage_tile(0, 0, tid, smb);
#pragma unroll
    for (int it = 0; it < 16; ++it) {
        int f = tid + it * 256;
        int m = f >> 6, q = f & 63;
        int half = q >> 5, v = q & 31;
        uint4 val = (half ? g_elo4 : g_ehi4)[(size_t)(rowBase + m) * 32 + v];
        uint32_t off = (uint32_t)(m * 1024 + half * 512 + v * 16);
        off ^= (uint32_t)(m & 7) << 4;
        *(uint4*)(smem + SM_A + off) = val;
    }

    // per-thread row metadata (4 rows: lane>>2 + {0,8,16,24} within warp-m tile)
    float bi[4]; int labi[4], jsel[4], rowg[4];
    float lm[4], ls[4];
#pragma unroll
    for (int r = 0; r < 4; ++r) {
        int rloc = wm * 32 + (lane >> 2) + (r & 1) * 8 + (r >> 1) * 16;
        rowg[r] = rowBase + rloc;
        bi[r]   = g_basec[rowg[r]];
        labi[r] = g_lab[rowg[r]];
        jsel[r] = g_jsel[rowg[r]];
        lm[r] = -1e30f; ls[r] = 0.f;
    }

    // fragment address precompute
    const int arow = wm * 32 + (lane & 15);
    const uint32_t aswz = (uint32_t)(lane & 7) << 4;
    const uint32_t aoff0 = (uint32_t)(arow * 1024 + ((lane >> 4) * 16));
    const int brow = ((lane >> 4) << 3) + (lane & 7);
    const uint32_t boff0 = (uint32_t)((wn * 32 + brow) * 512 + (((lane >> 3) & 1) * 16));
    const int cq = 2 * (lane & 3);

    for (int ct = 0; ct < NT; ++ct) {
        int p = ct & 1;
        if (ct + 1 < NT) { stage_tile(ct + 1, p ^ 1, tid, smb); cp_wait<1>(); }
        else             { cp_wait<0>(); }
        __syncthreads();

        uint32_t bbuf = smb + SM_B0 + (uint32_t)p * 65536u;
        float acc[2][4][4];
#pragma unroll
        for (int mf = 0; mf < 2; ++mf)
#pragma unroll
            for (int nf = 0; nf < 4; ++nf)
#pragma unroll
                for (int e = 0; e < 4; ++e) acc[mf][nf][e] = 0.f;

#pragma unroll 8
        for (int ks = 0; ks < KSTEPS; ++ks) {
            uint32_t a[2][4], b[4][2];
#pragma unroll
            for (int mf = 0; mf < 2; ++mf) {
                uint32_t off = (aoff0 + (uint32_t)(mf * 16384 + ks * 32)) ^ aswz;
                ldsm4(a[mf][0], a[mf][1], a[mf][2], a[mf][3], smb + SM_A + off);
            }
#pragma unroll
            for (int nf2 = 0; nf2 < 2; ++nf2) {
                uint32_t off = (boff0 + (uint32_t)(nf2 * 8192 + (ks & 15) * 32)) ^ aswz;
                uint32_t t0, t1, t2, t3;
                ldsm4(t0, t1, t2, t3, bbuf + off);
                b[nf2 * 2][0] = t0; b[nf2 * 2][1] = t1;
                b[nf2 * 2 + 1][0] = t2; b[nf2 * 2 + 1][1] = t3;
            }
#pragma unroll
            for (int mf = 0; mf < 2; ++mf)
#pragma unroll
                for (int nf = 0; nf < 4; ++nf)
                    mma16816(acc[mf][nf], a[mf], b[nf]);
        }

        // fused epilogue: fold this 64x128 gram tile into per-row logsumexp
        const float* mBase = (const float*)(smem + SM_META + p * 1024);
        const int*   mLab  = (const int*)(smem + SM_META + p * 1024 + 512);
#pragma unroll
        for (int r = 0; r < 4; ++r) {
            int mf = r >> 1, hh = r & 1;
#pragma unroll
            for (int nf = 0; nf < 4; ++nf) {
#pragma unroll
                for (int e = 0; e < 2; ++e) {
                    int cl = wn * 32 + nf * 8 + cq + e;
                    float g = acc[mf][nf][hh * 2 + e];
                    float sim = fminf(fmaf(20.f, g, bi[r] + mBase[cl]), 0.f);
                    if (mLab[cl] != labi[r]) {
                        float d = sim - lm[r];
                        if (d > 0.f) { ls[r] = fmaf(ls[r], __expf(-d), 1.f); lm[r] = sim; }
                        else if (d > -87.f) ls[r] += __expf(d);
                    } else if (ct * BN + cl == jsel[r]) {
                        g_num[rowg[r]] = sim;
                    }
                }
            }
        }
        __syncthreads();   // everyone done with buf p before it is re-staged
    }

    // reduce across the quad (lanes sharing the same rows)
#pragma unroll
    for (int r = 0; r < 4; ++r) {
#pragma unroll
        for (int off = 1; off <= 2; off <<= 1) {
            float mo = __shfl_xor_sync(0xffffffffu, lm[r], off);
            float so = __shfl_xor_sync(0xffffffffu, ls[r], off);
            float mn = fmaxf(lm[r], mo);
            ls[r] = ls[r] * __expf(lm[r] - mn) + so * __expf(mo - mn);
            lm[r] = mn;
        }
    }
    // reduce across the 4 n-warps
    float2* red = (float2*)(smem + SM_RED);
    if ((lane & 3) == 0) {
#pragma unroll
        for (int r = 0; r < 4; ++r) {
            int rloc = wm * 32 + (lane >> 2) + (r & 1) * 8 + (r >> 1) * 16;
            red[wn * 64 + rloc] = make_float2(lm[r], ls[r]);
        }
    }
    __syncthreads();
    if (tid < 64) {
        float m = -1e30f;
#pragma unroll
        for (int w = 0; w < 4; ++w) m = fmaxf(m, red[w * 64 + tid].x);
        float s = 0.f;
#pragma unroll
        for (int w = 0; w < 4; ++w) {
            float2 v = red[w * 64 + tid];
            s += v.y * __expf(v.x - m);
        }
        g_den[rowBase + tid] = m + __logf(s);
    }
}

// ---------------- finalize: masked mean ------------------------------------
__global__ void finalize_kernel(float* __restrict__ out) {
    __shared__ double ssum[256];
    __shared__ int    scnt[256];
    int tid = threadIdx.x;
    double acc = 0.0; int cnt = 0;
    for (int r = tid; r < B; r += 256) {
        if (g_valid[r]) {
            acc += (double)(g_den[r] - g_num[r]);
            cnt++;
        }
    }
    ssum[tid] = acc; scnt[tid] = cnt;
    __syncthreads();
    for (int off = 128; off; off >>= 1) {
        if (tid < off) { ssum[tid] += ssum[tid + off]; scnt[tid] += scnt[tid + off]; }
        __syncthreads();
    }
    if (tid == 0)
        out[0] = (scnt[0] > 0) ? (float)(ssum[0] / (double)scnt[0]) : 0.0f;
}

// ---------------------------------------------------------------------------
extern "C" void kernel_launch(void* const* d_in, const int* in_sizes, int n_in,
                              void* d_out, int out_size) {
    const float* emb    = (const float*)d_in[0];
    const void*  labels = d_in[1];

    cudaFuncSetAttribute(main_kernel,
                         cudaFuncAttributeMaxDynamicSharedMemorySize, SM_TOTAL);

    detect_kernel<<<1, 256>>>((const unsigned*)labels);
    prep_kernel<<<B / 8, 256>>>(emb, labels);
    sortclass_kernel<<<1, 256>>>();
    select_kernel<<<B / 8, 256>>>();
    main_kernel<<<B / BM, 256, SM_TOTAL>>>();
    finalize_kernel<<<1, 256>>>((float*)d_out);
}

// round 8
// speedup vs baseline: 4.4062x; 1.3104x over previous
#include <cuda_runtime.h>
#include <cuda_bf16.h>
#include <cstdint>

#define B     8192
#define DDIM  256
#define BM    64
#define BN    128
#define NT    (B / BN)        // 64 col tiles
#define KSTEPS 16             // K = 256, pure bf16 hi
// SMEM layout (bytes)
#define SM_A    0             // 64 rows * 512 B   = 32768
#define SM_B0   32768         // 128 * 512 B       = 65536
#define SM_B1   98304
#define SM_META 163840        // 2 * (128 f32 base + 128 i32 lab) = 2048
#define SM_RED  165888        // 4 * 64 * float2 = 2048
#define SM_TOTAL 167936

// ---------------- scratch ----------------
__device__ uint4 g_ehi4[B * DDIM / 8];
__device__ float g_basec[B];     // -10 * ||x||^2
__device__ int   g_lab[B];
__device__ int   g_jsel[B];
__device__ int   g_valid[B];
__device__ float g_num[B];
__device__ float g_den[B];
__device__ int   g_lab64;
__device__ int   g_off[256];
__device__ int   g_cnt[256];
__device__ int   g_cls[B];

// ---------------- helpers ----------------
__device__ __forceinline__ uint32_t smem_u32(const void* p) {
    uint32_t a;
    asm("{ .reg .u64 t; cvta.to.shared.u64 t, %1; cvt.u32.u64 %0, t; }" : "=r"(a) : "l"(p));
    return a;
}
__device__ __forceinline__ void cpa16(uint32_t dst, const void* src) {
    asm volatile("cp.async.cg.shared.global [%0], [%1], 16;" :: "r"(dst), "l"(src));
}
__device__ __forceinline__ void cp_commit() { asm volatile("cp.async.commit_group;" ::: "memory"); }
template<int N> __device__ __forceinline__ void cp_wait() {
    asm volatile("cp.async.wait_group %0;" :: "n"(N) : "memory");
}
__device__ __forceinline__ void ldsm4(uint32_t& r0, uint32_t& r1, uint32_t& r2, uint32_t& r3, uint32_t a) {
    asm volatile("ldmatrix.sync.aligned.m8n8.x4.shared.b16 {%0,%1,%2,%3}, [%4];"
                 : "=r"(r0), "=r"(r1), "=r"(r2), "=r"(r3) : "r"(a));
}
__device__ __forceinline__ void mma16816(float* d, const uint32_t* a, const uint32_t* b) {
    asm volatile("mma.sync.aligned.m16n8k16.row.col.f32.bf16.bf16.f32 "
                 "{%0,%1,%2,%3}, {%4,%5,%6,%7}, {%8,%9}, {%0,%1,%2,%3};"
                 : "+f"(d[0]), "+f"(d[1]), "+f"(d[2]), "+f"(d[3])
                 : "r"(a[0]), "r"(a[1]), "r"(a[2]), "r"(a[3]), "r"(b[0]), "r"(b[1]));
}

// ------------- dtype detect: odd 32-bit words all zero <=> int64 ----------
__global__ void detect_kernel(const unsigned* __restrict__ words) {
    __shared__ unsigned sOr[256];
    unsigned v = 0;
    for (int k = threadIdx.x; k < B / 2; k += 256) v |= words[2 * k + 1];
    sOr[threadIdx.x] = v;
    __syncthreads();
    for (int off = 128; off; off >>= 1) {
        if (threadIdx.x < off) sOr[threadIdx.x] |= sOr[threadIdx.x + off];
        __syncthreads();
    }
    if (threadIdx.x == 0) g_lab64 = (sOr[0] == 0u) ? 1 : 0;
}

// ------------- prep: norms, labels, bf16 convert ---------------------------
__global__ void prep_kernel(const float* __restrict__ emb,
                            const void* __restrict__ labels) {
    int warp = (blockIdx.x * blockDim.x + threadIdx.x) >> 5;
    int lane = threadIdx.x & 31;
    if (warp >= B) return;
    const float* row = emb + (size_t)warp * DDIM;
    float x[8];
    {
        float4 a = *reinterpret_cast<const float4*>(row + lane * 8);
        float4 b = *reinterpret_cast<const float4*>(row + lane * 8 + 4);
        x[0]=a.x; x[1]=a.y; x[2]=a.z; x[3]=a.w; x[4]=b.x; x[5]=b.y; x[6]=b.z; x[7]=b.w;
    }
    float s = 0.f;
    unsigned hu[4];
#pragma unroll
    for (int e = 0; e < 8; e += 2) {
        __nv_bfloat16 h0 = __float2bfloat16(x[e]);
        __nv_bfloat16 h1 = __float2bfloat16(x[e + 1]);
        hu[e >> 1] = (unsigned)__bfloat16_as_ushort(h0) | ((unsigned)__bfloat16_as_ushort(h1) << 16);
        s = fmaf(x[e], x[e], s);
        s = fmaf(x[e + 1], x[e + 1], s);
    }
    g_ehi4[warp * 32 + lane] = make_uint4(hu[0], hu[1], hu[2], hu[3]);
#pragma unroll
    for (int off = 16; off; off >>= 1) s += __shfl_xor_sync(0xffffffffu, s, off);
    if (lane == 0) {
        g_basec[warp] = -10.0f * s;
        int lab = g_lab64 ? (int)((const long long*)labels)[warp]
                          : ((const int*)labels)[warp];
        g_lab[warp] = lab;
    }
}

// ------------- class bucketing -------------
__global__ void sortclass_kernel() {
    __shared__ int h[256], off[256];
    int t = threadIdx.x;
    h[t] = 0;
    __syncthreads();
    for (int i = t; i < B; i += 256) atomicAdd(&h[g_lab[i] & 255], 1);
    __syncthreads();
    if (t == 0) {
        int acc = 0;
        for (int c = 0; c < 256; ++c) { off[c] = acc; acc += h[c]; }
    }
    __syncthreads();
    g_cnt[t] = h[t];
    g_off[t] = off[t];
    h[t] = off[t];
    __syncthreads();
    for (int i = t; i < B; i += 256) {
        int pos = atomicAdd(&h[g_lab[i] & 255], 1);
        g_cls[pos] = i;
    }
}

// ------- threefry2x32, JAX partitionable mode, key=(0,42) ------------------
__device__ __forceinline__ unsigned rotl32(unsigned x, int r) {
    return __funnelshift_l(x, x, r);
}
__device__ __forceinline__ unsigned threefry_bits(unsigned idx) {
    const unsigned ks0 = 0u, ks1 = 42u, ks2 = 0u ^ 42u ^ 0x1BD11BDAu;
    unsigned x0 = 0u + ks0, x1 = idx + ks1;
#define TFR(r) { x0 += x1; x1 = rotl32(x1, r); x1 ^= x0; }
    TFR(13) TFR(15) TFR(26) TFR(6)   x0 += ks1; x1 += ks2 + 1u;
    TFR(17) TFR(29) TFR(16) TFR(24)  x0 += ks2; x1 += ks0 + 2u;
    TFR(13) TFR(15) TFR(26) TFR(6)   x0 += ks0; x1 += ks1 + 3u;
    TFR(17) TFR(29) TFR(16) TFR(24)  x0 += ks1; x1 += ks2 + 4u;
    TFR(13) TFR(15) TFR(26) TFR(6)   x0 += ks2; x1 += ks0 + 5u;
#undef TFR
    return x0 ^ x1;
}

// ------------- positive selection: warp per row over its class list --------
__global__ void select_kernel() {
    int warp = (blockIdx.x * blockDim.x + threadIdx.x) >> 5;
    int lane = threadIdx.x & 31;
    if (warp >= B) return;
    int i = warp;
    int lab = g_lab[i] & 255;
    int base = g_off[lab], n = g_cnt[lab];
    unsigned bv = 0; int bj = -1;
    for (int t = lane; t < n; t += 32) {
        int j = g_cls[base + t];
        if (j == i) continue;
        unsigned v = threefry_bits((unsigned)(i * B + j)) >> 9;
        if (bj < 0 || v > bv || (v == bv && j < bj)) { bv = v; bj = j; }
    }
    const unsigned full = 0xffffffffu;
#pragma unroll
    for (int off = 16; off; off >>= 1) {
        unsigned ov = __shfl_down_sync(full, bv, off);
        int oj = __shfl_down_sync(full, bj, off);
        if (oj >= 0 && (bj < 0 || ov > bv || (ov == bv && oj < bj))) { bv = ov; bj = oj; }
    }
    if (lane == 0) {
        g_jsel[i] = bj;
        g_valid[i] = (n - 1 > 0) && (B - n > 0);
    }
}

// ------------- exact fp32 numerator: one dot per row -----------------------
__global__ void num_kernel(const float* __restrict__ emb) {
    int warp = (blockIdx.x * blockDim.x + threadIdx.x) >> 5;
    int lane = threadIdx.x & 31;
    if (warp >= B) return;
    int j = g_jsel[warp];
    if (j < 0) { if (lane == 0) g_num[warp] = 0.f; return; }
    const float* xi = emb + (size_t)warp * DDIM;
    const float* xj = emb + (size_t)j * DDIM;
    float g = 0.f;
#pragma unroll
    for (int k = 0; k < 8; k += 4) {
        float4 a = *reinterpret_cast<const float4*>(xi + lane * 8 + k);
        float4 b = *reinterpret_cast<const float4*>(xj + lane * 8 + k);
        g = fmaf(a.x, b.x, g); g = fmaf(a.y, b.y, g);
        g = fmaf(a.z, b.z, g); g = fmaf(a.w, b.w, g);
    }
#pragma unroll
    for (int off = 16; off; off >>= 1) g += __shfl_xor_sync(0xffffffffu, g, off);
    if (lane == 0)
        g_num[warp] = fminf(fmaf(20.f, g, g_basec[warp] + g_basec[j]), 0.f);
}

// ------------- main: bf16 HMMA Gram + fused masked logsumexp ---------------
__device__ __forceinline__ void stage_tile(int ct, int p, int tid, uint32_t smb) {
    int c0 = ct * BN;
    uint32_t bbuf = smb + SM_B0 + (uint32_t)p * 65536u;
#pragma unroll
    for (int it = 0; it < 16; ++it) {
        int f = tid + it * 256;
        int n = f >> 5, v = f & 31;
        uint32_t off = (uint32_t)(n * 512 + v * 16);
        off ^= (uint32_t)(n & 7) << 4;
        cpa16(bbuf + off, g_ehi4 + (size_t)(c0 + n) * 32 + v);
    }
    uint32_t mbuf = smb + SM_META + (uint32_t)p * 1024u;
    if (tid < 32)      cpa16(mbuf + tid * 16, (const char*)g_basec + (size_t)c0 * 4 + tid * 16);
    else if (tid < 64) cpa16(mbuf + 512 + (tid - 32) * 16, (const char*)g_lab + (size_t)c0 * 4 + (tid - 32) * 16);
    cp_commit();
}

__global__ void __launch_bounds__(256, 1)
main_kernel() {
    extern __shared__ char smem[];
    const uint32_t smb = smem_u32(smem);
    const int tid = threadIdx.x;
    const int lane = tid & 31, wid = tid >> 5;
    const int wm = wid >> 2, wn = wid & 3;
    const int rowBase = blockIdx.x * BM;

    // prologue: kick off tile 0, stage A while it flies
    stage_tile(0, 0, tid, smb);
#pragma unroll
    for (int it = 0; it < 8; ++it) {
        int f = tid + it * 256;
        int m = f >> 5, v = f & 31;
        uint4 val = g_ehi4[(size_t)(rowBase + m) * 32 + v];
        uint32_t off = (uint32_t)(m * 512 + v * 16);
        off ^= (uint32_t)(m & 7) << 4;
        *(uint4*)(smem + SM_A + off) = val;
    }

    // per-thread row metadata (4 rows within warp-m tile)
    float bi[4]; int labi[4];
    float lm[4], ls[4];
#pragma unroll
    for (int r = 0; r < 4; ++r) {
        int rloc = wm * 32 + (lane >> 2) + (r & 1) * 8 + (r >> 1) * 16;
        int rg = rowBase + rloc;
        bi[r]   = g_basec[rg];
        labi[r] = g_lab[rg];
        lm[r] = -1e30f; ls[r] = 0.f;
    }

    // fragment address precompute
    const int arow = wm * 32 + (lane & 15);
    const uint32_t aswz = (uint32_t)(lane & 7) << 4;
    const uint32_t aoff0 = (uint32_t)(arow * 512 + ((lane >> 4) * 16));
    const int brow = ((lane >> 4) << 3) + (lane & 7);
    const uint32_t boff0 = (uint32_t)((wn * 32 + brow) * 512 + (((lane >> 3) & 1) * 16));
    const int cq = 2 * (lane & 3);

    for (int ct = 0; ct < NT; ++ct) {
        int p = ct & 1;
        if (ct + 1 < NT) { stage_tile(ct + 1, p ^ 1, tid, smb); cp_wait<1>(); }
        else             { cp_wait<0>(); }
        __syncthreads();

        uint32_t bbuf = smb + SM_B0 + (uint32_t)p * 65536u;
        float acc[2][4][4];
#pragma unroll
        for (int mf = 0; mf < 2; ++mf)
#pragma unroll
            for (int nf = 0; nf < 4; ++nf)
#pragma unroll
                for (int e = 0; e < 4; ++e) acc[mf][nf][e] = 0.f;

#pragma unroll 8
        for (int ks = 0; ks < KSTEPS; ++ks) {
            uint32_t a[2][4], b[4][2];
#pragma unroll
            for (int mf = 0; mf < 2; ++mf) {
                uint32_t off = (aoff0 + (uint32_t)(mf * 8192 + ks * 32)) ^ aswz;
                ldsm4(a[mf][0], a[mf][1], a[mf][2], a[mf][3], smb + SM_A + off);
            }
#pragma unroll
            for (int nf2 = 0; nf2 < 2; ++nf2) {
                uint32_t off = (boff0 + (uint32_t)(nf2 * 8192 + ks * 32)) ^ aswz;
                uint32_t t0, t1, t2, t3;
                ldsm4(t0, t1, t2, t3, bbuf + off);
                b[nf2 * 2][0] = t0; b[nf2 * 2][1] = t1;
                b[nf2 * 2 + 1][0] = t2; b[nf2 * 2 + 1][1] = t3;
            }
#pragma unroll
            for (int mf = 0; mf < 2; ++mf)
#pragma unroll
                for (int nf = 0; nf < 4; ++nf)
                    mma16816(acc[mf][nf], a[mf], b[nf]);
        }

        // fused epilogue: fold this 64x128 gram tile into per-row logsumexp
        const float* mBase = (const float*)(smem + SM_META + p * 1024);
        const int*   mLab  = (const int*)(smem + SM_META + p * 1024 + 512);
#pragma unroll
        for (int r = 0; r < 4; ++r) {
            int mf = r >> 1, hh = r & 1;
#pragma unroll
            for (int nf = 0; nf < 4; ++nf) {
#pragma unroll
                for (int e = 0; e < 2; ++e) {
                    int cl = wn * 32 + nf * 8 + cq + e;
                    float g = acc[mf][nf][hh * 2 + e];
                    float sim = fminf(fmaf(20.f, g, bi[r] + mBase[cl]), 0.f);
                    if (mLab[cl] != labi[r]) {
                        float d = sim - lm[r];
                        if (d > 0.f) { ls[r] = fmaf(ls[r], __expf(-d), 1.f); lm[r] = sim; }
                        else if (d > -87.f) ls[r] += __expf(d);
                    }
                }
            }
        }
        __syncthreads();   // everyone done with buf p before it is re-staged
    }

    // reduce across the quad (lanes sharing the same rows)
#pragma unroll
    for (int r = 0; r < 4; ++r) {
#pragma unroll
        for (int off = 1; off <= 2; off <<= 1) {
            float mo = __shfl_xor_sync(0xffffffffu, lm[r], off);
            float so = __shfl_xor_sync(0xffffffffu, ls[r], off);
            float mn = fmaxf(lm[r], mo);
            ls[r] = ls[r] * __expf(lm[r] - mn) + so * __expf(mo - mn);
            lm[r] = mn;
        }
    }
    // reduce across the 4 n-warps
    float2* red = (float2*)(smem + SM_RED);
    if ((lane & 3) == 0) {
#pragma unroll
        for (int r = 0; r < 4; ++r) {
            int rloc = wm * 32 + (lane >> 2) + (r & 1) * 8 + (r >> 1) * 16;
            red[wn * 64 + rloc] = make_float2(lm[r], ls[r]);
        }
    }
    __syncthreads();
    if (tid < 64) {
        float m = -1e30f;
#pragma unroll
        for (int w = 0; w < 4; ++w) m = fmaxf(m, red[w * 64 + tid].x);
        float s = 0.f;
#pragma unroll
        for (int w = 0; w < 4; ++w) {
            float2 v = red[w * 64 + tid];
            s += v.y * __expf(v.x - m);
        }
        g_den[rowBase + tid] = m + __logf(s);
    }
}

// ---------------- finalize: masked mean ------------------------------------
__global__ void finalize_kernel(float* __restrict__ out) {
    __shared__ double ssum[256];
    __shared__ int    scnt[256];
    int tid = threadIdx.x;
    double acc = 0.0; int cnt = 0;
    for (int r = tid; r < B; r += 256) {
        if (g_valid[r]) {
            acc += (double)(g_den[r] - g_num[r]);
            cnt++;
        }
    }
    ssum[tid] = acc; scnt[tid] = cnt;
    __syncthreads();
    for (int off = 128; off; off >>= 1) {
        if (tid < off) { ssum[tid] += ssum[tid + off]; scnt[tid] += scnt[tid + off]; }
        __syncthreads();
    }
    if (tid == 0)
        out[0] = (scnt[0] > 0) ? (float)(ssum[0] / (double)scnt[0]) : 0.0f;
}

// ---------------------------------------------------------------------------
extern "C" void kernel_launch(void* const* d_in, const int* in_sizes, int n_in,
                              void* d_out, int out_size) {
    const float* emb    = (const float*)d_in[0];
    const void*  labels = d_in[1];

    cudaFuncSetAttribute(main_kernel,
                         cudaFuncAttributeMaxDynamicSharedMemorySize, SM_TOTAL);

    detect_kernel<<<1, 256>>>((const unsigned*)labels);
    prep_kernel<<<B / 8, 256>>>(emb, labels);
    sortclass_kernel<<<1, 256>>>();
    select_kernel<<<B / 8, 256>>>();
    num_kernel<<<B / 8, 256>>>(emb);
    main_kernel<<<B / BM, 256, SM_TOTAL>>>();
    finalize_kernel<<<1, 256>>>((float*)d_out);
}

// round 10
// speedup vs baseline: 4.8582x; 1.1026x over previous
#include <cuda_runtime.h>
#include <cuda_bf16.h>
#include <cstdint>

#define B     8192
#define DDIM  256
#define BM    64
#define BN    64
#define COLSPLIT 2
#define COLS_PER_CTA (B / COLSPLIT)   // 4096
#define NT    (COLS_PER_CTA / BN)     // 64 col tiles
#define KSTEPS 16                     // K = 256, pure bf16 hi
// SMEM layout (bytes)
#define SM_A    0                     // 64 rows * 512 B = 32768
#define SM_B0   32768                 // 64 * 512 B = 32768
#define SM_B1   65536
#define SM_META 98304                 // 2 * (64 f32 base + 64 i32 lab) = 1024
#define SM_RED  99328                 // 4 * 64 * float2 = 2048
#define SM_TOTAL 101376

// ---------------- scratch ----------------
__device__ uint4 g_ehi4[B * DDIM / 8];
__device__ float g_basec[B];     // -10 * ||x||^2
__device__ int   g_lab[B];
__device__ int   g_jsel[B];
__device__ int   g_valid[B];
__device__ float g_num[B];
__device__ float g_pm[COLSPLIT][B];
__device__ float g_ps[COLSPLIT][B];
__device__ int   g_lab64;
__device__ int   g_off[256];
__device__ int   g_cnt[256];
__device__ int   g_cls[B];

// ---------------- helpers ----------------
__device__ __forceinline__ uint32_t smem_u32(const void* p) {
    uint32_t a;
    asm("{ .reg .u64 t; cvta.to.shared.u64 t, %1; cvt.u32.u64 %0, t; }" : "=r"(a) : "l"(p));
    return a;
}
__device__ __forceinline__ void cpa16(uint32_t dst, const void* src) {
    asm volatile("cp.async.cg.shared.global [%0], [%1], 16;" :: "r"(dst), "l"(src));
}
__device__ __forceinline__ void cp_commit() { asm volatile("cp.async.commit_group;" ::: "memory"); }
template<int N> __device__ __forceinline__ void cp_wait() {
    asm volatile("cp.async.wait_group %0;" :: "n"(N) : "memory");
}
__device__ __forceinline__ void ldsm4(uint32_t& r0, uint32_t& r1, uint32_t& r2, uint32_t& r3, uint32_t a) {
    asm volatile("ldmatrix.sync.aligned.m8n8.x4.shared.b16 {%0,%1,%2,%3}, [%4];"
                 : "=r"(r0), "=r"(r1), "=r"(r2), "=r"(r3) : "r"(a));
}
__device__ __forceinline__ void mma16816(float* d, const uint32_t* a, const uint32_t* b) {
    asm volatile("mma.sync.aligned.m16n8k16.row.col.f32.bf16.bf16.f32 "
                 "{%0,%1,%2,%3}, {%4,%5,%6,%7}, {%8,%9}, {%0,%1,%2,%3};"
                 : "+f"(d[0]), "+f"(d[1]), "+f"(d[2]), "+f"(d[3])
                 : "r"(a[0]), "r"(a[1]), "r"(a[2]), "r"(a[3]), "r"(b[0]), "r"(b[1]));
}

// ------------- dtype detect: odd 32-bit words all zero <=> int64 ----------
__global__ void detect_kernel(const unsigned* __restrict__ words) {
    __shared__ unsigned sOr[256];
    unsigned v = 0;
    for (int k = threadIdx.x; k < B / 2; k += 256) v |= words[2 * k + 1];
    sOr[threadIdx.x] = v;
    __syncthreads();
    for (int off = 128; off; off >>= 1) {
        if (threadIdx.x < off) sOr[threadIdx.x] |= sOr[threadIdx.x + off];
        __syncthreads();
    }
    if (threadIdx.x == 0) g_lab64 = (sOr[0] == 0u) ? 1 : 0;
}

// ------------- prep: norms, labels, bf16 convert ---------------------------
__global__ void prep_kernel(const float* __restrict__ emb,
                            const void* __restrict__ labels) {
    int warp = (blockIdx.x * blockDim.x + threadIdx.x) >> 5;
    int lane = threadIdx.x & 31;
    if (warp >= B) return;
    const float* row = emb + (size_t)warp * DDIM;
    float x[8];
    {
        float4 a = *reinterpret_cast<const float4*>(row + lane * 8);
        float4 b = *reinterpret_cast<const float4*>(row + lane * 8 + 4);
        x[0]=a.x; x[1]=a.y; x[2]=a.z; x[3]=a.w; x[4]=b.x; x[5]=b.y; x[6]=b.z; x[7]=b.w;
    }
    float s = 0.f;
    unsigned hu[4];
#pragma unroll
    for (int e = 0; e < 8; e += 2) {
        __nv_bfloat16 h0 = __float2bfloat16(x[e]);
        __nv_bfloat16 h1 = __float2bfloat16(x[e + 1]);
        hu[e >> 1] = (unsigned)__bfloat16_as_ushort(h0) | ((unsigned)__bfloat16_as_ushort(h1) << 16);
        s = fmaf(x[e], x[e], s);
        s = fmaf(x[e + 1], x[e + 1], s);
    }
    g_ehi4[warp * 32 + lane] = make_uint4(hu[0], hu[1], hu[2], hu[3]);
#pragma unroll
    for (int off = 16; off; off >>= 1) s += __shfl_xor_sync(0xffffffffu, s, off);
    if (lane == 0) {
        g_basec[warp] = -10.0f * s;
        int lab = g_lab64 ? (int)((const long long*)labels)[warp]
                          : ((const int*)labels)[warp];
        g_lab[warp] = lab;
    }
}

// ------------- class bucketing -------------
__global__ void sortclass_kernel() {
    __shared__ int h[256], off[256];
    int t = threadIdx.x;
    h[t] = 0;
    __syncthreads();
    for (int i = t; i < B; i += 256) atomicAdd(&h[g_lab[i] & 255], 1);
    __syncthreads();
    if (t == 0) {
        int acc = 0;
        for (int c = 0; c < 256; ++c) { off[c] = acc; acc += h[c]; }
    }
    __syncthreads();
    g_cnt[t] = h[t];
    g_off[t] = off[t];
    h[t] = off[t];
    __syncthreads();
    for (int i = t; i < B; i += 256) {
        int pos = atomicAdd(&h[g_lab[i] & 255], 1);
        g_cls[pos] = i;
    }
}

// ------- threefry2x32, JAX partitionable mode, key=(0,42) ------------------
__device__ __forceinline__ unsigned rotl32(unsigned x, int r) {
    return __funnelshift_l(x, x, r);
}
__device__ __forceinline__ unsigned threefry_bits(unsigned idx) {
    const unsigned ks0 = 0u, ks1 = 42u, ks2 = 0u ^ 42u ^ 0x1BD11BDAu;
    unsigned x0 = 0u + ks0, x1 = idx + ks1;
#define TFR(r) { x0 += x1; x1 = rotl32(x1, r); x1 ^= x0; }
    TFR(13) TFR(15) TFR(26) TFR(6)   x0 += ks1; x1 += ks2 + 1u;
    TFR(17) TFR(29) TFR(16) TFR(24)  x0 += ks2; x1 += ks0 + 2u;
    TFR(13) TFR(15) TFR(26) TFR(6)   x0 += ks0; x1 += ks1 + 3u;
    TFR(17) TFR(29) TFR(16) TFR(24)  x0 += ks1; x1 += ks2 + 4u;
    TFR(13) TFR(15) TFR(26) TFR(6)   x0 += ks2; x1 += ks0 + 5u;
#undef TFR
    return x0 ^ x1;
}

// ------------- positive selection: warp per row over its class list --------
__global__ void select_kernel() {
    int warp = (blockIdx.x * blockDim.x + threadIdx.x) >> 5;
    int lane = threadIdx.x & 31;
    if (warp >= B) return;
    int i = warp;
    int lab = g_lab[i] & 255;
    int base = g_off[lab], n = g_cnt[lab];
    unsigned bv = 0; int bj = -1;
    for (int t = lane; t < n; t += 32) {
        int j = g_cls[base + t];
        if (j == i) continue;
        unsigned v = threefry_bits((unsigned)(i * B + j)) >> 9;
        if (bj < 0 || v > bv || (v == bv && j < bj)) { bv = v; bj = j; }
    }
    const unsigned full = 0xffffffffu;
#pragma unroll
    for (int off = 16; off; off >>= 1) {
        unsigned ov = __shfl_down_sync(full, bv, off);
        int oj = __shfl_down_sync(full, bj, off);
        if (oj >= 0 && (bj < 0 || ov > bv || (ov == bv && oj < bj))) { bv = ov; bj = oj; }
    }
    if (lane == 0) {
        g_jsel[i] = bj;
        g_valid[i] = (n - 1 > 0) && (B - n > 0);
    }
}

// ------------- exact fp32 numerator: one dot per row -----------------------
__global__ void num_kernel(const float* __restrict__ emb) {
    int warp = (blockIdx.x * blockDim.x + threadIdx.x) >> 5;
    int lane = threadIdx.x & 31;
    if (warp >= B) return;
    int j = g_jsel[warp];
    if (j < 0) { if (lane == 0) g_num[warp] = 0.f; return; }
    const float* xi = emb + (size_t)warp * DDIM;
    const float* xj = emb + (size_t)j * DDIM;
    float g = 0.f;
#pragma unroll
    for (int k = 0; k < 8; k += 4) {
        float4 a = *reinterpret_cast<const float4*>(xi + lane * 8 + k);
        float4 b = *reinterpret_cast<const float4*>(xj + lane * 8 + k);
        g = fmaf(a.x, b.x, g); g = fmaf(a.y, b.y, g);
        g = fmaf(a.z, b.z, g); g = fmaf(a.w, b.w, g);
    }
#pragma unroll
    for (int off = 16; off; off >>= 1) g += __shfl_xor_sync(0xffffffffu, g, off);
    if (lane == 0)
        g_num[warp] = fminf(fmaf(20.f, g, g_basec[warp] + g_basec[j]), 0.f);
}

// ------------- main: bf16 HMMA Gram + fused masked logsumexp ---------------
__device__ __forceinline__ void stage_tile(int c0, int p, int tid, uint32_t smb) {
    uint32_t bbuf = smb + SM_B0 + (uint32_t)p * 32768u;
#pragma unroll
    for (int it = 0; it < 8; ++it) {
        int f = tid + it * 256;
        int n = f >> 5, v = f & 31;
        uint32_t off = (uint32_t)(n * 512 + v * 16);
        off ^= (uint32_t)(n & 7) << 4;
        cpa16(bbuf + off, g_ehi4 + (size_t)(c0 + n) * 32 + v);
    }
    uint32_t mbuf = smb + SM_META + (uint32_t)p * 512u;
    if (tid < 16)      cpa16(mbuf + tid * 16, (const char*)g_basec + (size_t)c0 * 4 + tid * 16);
    else if (tid < 32) cpa16(mbuf + 256 + (tid - 16) * 16, (const char*)g_lab + (size_t)c0 * 4 + (tid - 16) * 16);
    cp_commit();
}

__global__ void __launch_bounds__(256, 2)
main_kernel() {
    extern __shared__ char smem[];
    const uint32_t smb = smem_u32(smem);
    const int tid = threadIdx.x;
    const int lane = tid & 31, wid = tid >> 5;
    const int wm = wid >> 2, wn = wid & 3;
    const int rowBase = blockIdx.y * BM;
    const int colBase = blockIdx.x * COLS_PER_CTA;
    const int split = blockIdx.x;

    // prologue: kick off tile 0, stage A while it flies
    stage_tile(colBase, 0, tid, smb);
#pragma unroll
    for (int it = 0; it < 8; ++it) {
        int f = tid + it * 256;
        int m = f >> 5, v = f & 31;
        uint4 val = g_ehi4[(size_t)(rowBase + m) * 32 + v];
        uint32_t off = (uint32_t)(m * 512 + v * 16);
        off ^= (uint32_t)(m & 7) << 4;
        *(uint4*)(smem + SM_A + off) = val;
    }

    // per-thread row metadata (4 rows within warp-m tile)
    float bi[4]; int labi[4];
    float lm[4], ls[4];
#pragma unroll
    for (int r = 0; r < 4; ++r) {
        int rloc = wm * 32 + (lane >> 2) + (r & 1) * 8 + (r >> 1) * 16;
        int rg = rowBase + rloc;
        bi[r]   = g_basec[rg];
        labi[r] = g_lab[rg];
        lm[r] = -1e30f; ls[r] = 0.f;
    }

    // fragment address precompute
    const int arow = wm * 32 + (lane & 15);
    const uint32_t aswz = (uint32_t)(lane & 7) << 4;
    const uint32_t aoff0 = (uint32_t)(arow * 512 + ((lane >> 4) * 16));
    const int brow = ((lane >> 4) << 3) + (lane & 7);
    const uint32_t boff0 = (uint32_t)((wn * 16 + brow) * 512 + (((lane >> 3) & 1) * 16));
    const int cq = 2 * (lane & 3);

    for (int ct = 0; ct < NT; ++ct) {
        int p = ct & 1;
        if (ct + 1 < NT) { stage_tile(colBase + (ct + 1) * BN, p ^ 1, tid, smb); cp_wait<1>(); }
        else             { cp_wait<0>(); }
        __syncthreads();

        uint32_t bbuf = smb + SM_B0 + (uint32_t)p * 32768u;
        float acc[2][2][4];
#pragma unroll
        for (int mf = 0; mf < 2; ++mf)
#pragma unroll
            for (int nf = 0; nf < 2; ++nf)
#pragma unroll
                for (int e = 0; e < 4; ++e) acc[mf][nf][e] = 0.f;

#pragma unroll
        for (int ks = 0; ks < KSTEPS; ++ks) {
            uint32_t a[2][4], b[2][2];
#pragma unroll
            for (int mf = 0; mf < 2; ++mf) {
                uint32_t off = (aoff0 + (uint32_t)(mf * 8192 + ks * 32)) ^ aswz;
                ldsm4(a[mf][0], a[mf][1], a[mf][2], a[mf][3], smb + SM_A + off);
            }
            {
                uint32_t off = (boff0 + (uint32_t)(ks * 32)) ^ aswz;
                uint32_t t0, t1, t2, t3;
                ldsm4(t0, t1, t2, t3, bbuf + off);
                b[0][0] = t0; b[0][1] = t1;
                b[1][0] = t2; b[1][1] = t3;
            }
#pragma unroll
            for (int mf = 0; mf < 2; ++mf)
#pragma unroll
                for (int nf = 0; nf < 2; ++nf)
                    mma16816(acc[mf][nf], a[mf], b[nf]);
        }

        // fused epilogue: fold this 64x64 gram tile into per-row logsumexp
        const float* mBase = (const float*)(smem + SM_META + p * 512);
        const int*   mLab  = (const int*)(smem + SM_META + p * 512 + 256);
#pragma unroll
        for (int r = 0; r < 4; ++r) {
            int mf = r >> 1, hh = r & 1;
#pragma unroll
            for (int nf = 0; nf < 2; ++nf) {
#pragma unroll
                for (int e = 0; e < 2; ++e) {
                    int cl = wn * 16 + nf * 8 + cq + e;
                    float g = acc[mf][nf][hh * 2 + e];
                    float sim = fminf(fmaf(20.f, g, bi[r] + mBase[cl]), 0.f);
                    if (mLab[cl] != labi[r]) {
                        float d = sim - lm[r];
                        if (d > 0.f) { ls[r] = fmaf(ls[r], __expf(-d), 1.f); lm[r] = sim; }
                        else if (d > -87.f) ls[r] += __expf(d);
                    }
                }
            }
        }
        __syncthreads();   // everyone done with buf p before it is re-staged
    }

    // reduce across the quad (lanes sharing the same rows)
#pragma unroll
    for (int r = 0; r < 4; ++r) {
#pragma unroll
        for (int off = 1; off <= 2; off <<= 1) {
            float mo = __shfl_xor_sync(0xffffffffu, lm[r], off);
            float so = __shfl_xor_sync(0xffffffffu, ls[r], off);
            float mn = fmaxf(lm[r], mo);
            ls[r] = ls[r] * __expf(lm[r] - mn) + so * __expf(mo - mn);
            lm[r] = mn;
        }
    }
    // reduce across the 4 n-warps
    float2* red = (float2*)(smem + SM_RED);
    if ((lane & 3) == 0) {
#pragma unroll
        for (int r = 0; r < 4; ++r) {
            int rloc = wm * 32 + (lane >> 2) + (r & 1) * 8 + (r >> 1) * 16;
            red[wn * 64 + rloc] = make_float2(lm[r], ls[r]);
        }
    }
    __syncthreads();
    if (tid < 64) {
        float m = -1e30f;
#pragma unroll
        for (int w = 0; w < 4; ++w) m = fmaxf(m, red[w * 64 + tid].x);
        float s = 0.f;
#pragma unroll
        for (int w = 0; w < 4; ++w) {
            float2 v = red[w * 64 + tid];
            s += v.y * __expf(v.x - m);
        }
        g_pm[split][rowBase + tid] = m;
        g_ps[split][rowBase + tid] = s;
    }
}

// ---------------- finalize: combine splits, masked mean --------------------
__global__ void finalize_kernel(float* __restrict__ out) {
    __shared__ double ssum[256];
    __shared__ int    scnt[256];
    int tid = threadIdx.x;
    double acc = 0.0; int cnt = 0;
    for (int r = tid; r < B; r += 256) {
        if (g_valid[r]) {
            float m0 = g_pm[0][r], m1 = g_pm[1][r];
            float m = fmaxf(m0, m1);
            float s = g_ps[0][r] * __expf(m0 - m) + g_ps[1][r] * __expf(m1 - m);
            float denom = m + __logf(s);
            acc += (double)(denom - g_num[r]);
            cnt++;
        }
    }
    ssum[tid] = acc; scnt[tid] = cnt;
    __syncthreads();
    for (int off = 128; off; off >>= 1) {
        if (tid < off) { ssum[tid] += ssum[tid + off]; scnt[tid] += scnt[tid + off]; }
        __syncthreads();
    }
    if (tid == 0)
        out[0] = (scnt[0] > 0) ? (float)(ssum[0] / (double)scnt[0]) : 0.0f;
}

// ---------------------------------------------------------------------------
extern "C" void kernel_launch(void* const* d_in, const int* in_sizes, int n_in,
                              void* d_out, int out_size) {
    const float* emb    = (const float*)d_in[0];
    const void*  labels = d_in[1];

    cudaFuncSetAttribute(main_kernel,
                         cudaFuncAttributeMaxDynamicSharedMemorySize, SM_TOTAL);

    detect_kernel<<<1, 256>>>((const unsigned*)labels);
    prep_kernel<<<B / 8, 256>>>(emb, labels);
    sortclass_kernel<<<1, 256>>>();
    select_kernel<<<B / 8, 256>>>();
    num_kernel<<<B / 8, 256>>>(emb);
    main_kernel<<<dim3(COLSPLIT, B / BM), 256, SM_TOTAL>>>();
    finalize_kernel<<<1, 256>>>((float*)d_out);
}

// round 12
// speedup vs baseline: 5.2606x; 1.0828x over previous
#include <cuda_runtime.h>
#include <cuda_bf16.h>
#include <cstdint>

#define B     8192
#define DDIM  256
#define BM    64
#define BN    64
#define COLSPLIT 2
#define COLS_PER_CTA (B / COLSPLIT)   // 4096
#define NT    (COLS_PER_CTA / BN)     // 64 col tiles
#define KSTEPS 16                     // K = 256, pure bf16 hi
#define THREADS 128
// SMEM layout (bytes)
#define SM_A    0                     // 64 rows * 512 B = 32768
#define SM_B0   32768                 // 64 * 512 B = 32768
#define SM_B1   65536
#define SM_META 98304                 // 2 * (64 f32 base + 64 i32 lab) = 1024
#define SM_RED  99328                 // 2 * 64 * float2 = 1024
#define SM_TOTAL 100352

// ---------------- scratch ----------------
__device__ uint4 g_ehi4[B * DDIM / 8];
__device__ float g_basec[B];     // -10 * ||x||^2
__device__ int   g_lab[B];
__device__ int   g_jsel[B];
__device__ int   g_valid[B];
__device__ float g_num[B];
__device__ float g_pm[COLSPLIT][B];
__device__ float g_ps[COLSPLIT][B];
__device__ int   g_lab64;
__device__ int   g_off[256];
__device__ int   g_cnt[256];
__device__ int   g_cls[B];

// ---------------- helpers ----------------
__device__ __forceinline__ uint32_t smem_u32(const void* p) {
    uint32_t a;
    asm("{ .reg .u64 t; cvta.to.shared.u64 t, %1; cvt.u32.u64 %0, t; }" : "=r"(a) : "l"(p));
    return a;
}
__device__ __forceinline__ void cpa16(uint32_t dst, const void* src) {
    asm volatile("cp.async.cg.shared.global [%0], [%1], 16;" :: "r"(dst), "l"(src));
}
__device__ __forceinline__ void cp_commit() { asm volatile("cp.async.commit_group;" ::: "memory"); }
template<int N> __device__ __forceinline__ void cp_wait() {
    asm volatile("cp.async.wait_group %0;" :: "n"(N) : "memory");
}
__device__ __forceinline__ void ldsm4(uint32_t& r0, uint32_t& r1, uint32_t& r2, uint32_t& r3, uint32_t a) {
    asm volatile("ldmatrix.sync.aligned.m8n8.x4.shared.b16 {%0,%1,%2,%3}, [%4];"
                 : "=r"(r0), "=r"(r1), "=r"(r2), "=r"(r3) : "r"(a));
}
__device__ __forceinline__ void mma16816(float* d, const uint32_t* a, const uint32_t* b) {
    asm volatile("mma.sync.aligned.m16n8k16.row.col.f32.bf16.bf16.f32 "
                 "{%0,%1,%2,%3}, {%4,%5,%6,%7}, {%8,%9}, {%0,%1,%2,%3};"
                 : "+f"(d[0]), "+f"(d[1]), "+f"(d[2]), "+f"(d[3])
                 : "r"(a[0]), "r"(a[1]), "r"(a[2]), "r"(a[3]), "r"(b[0]), "r"(b[1]));
}

// ------------- dtype detect: odd 32-bit words all zero <=> int64 ----------
__global__ void detect_kernel(const unsigned* __restrict__ words) {
    __shared__ unsigned sOr[256];
    unsigned v = 0;
    for (int k = threadIdx.x; k < B / 2; k += 256) v |= words[2 * k + 1];
    sOr[threadIdx.x] = v;
    __syncthreads();
    for (int off = 128; off; off >>= 1) {
        if (threadIdx.x < off) sOr[threadIdx.x] |= sOr[threadIdx.x + off];
        __syncthreads();
    }
    if (threadIdx.x == 0) g_lab64 = (sOr[0] == 0u) ? 1 : 0;
}

// ------------- prep: norms, labels, bf16 convert ---------------------------
__global__ void prep_kernel(const float* __restrict__ emb,
                            const void* __restrict__ labels) {
    int warp = (blockIdx.x * blockDim.x + threadIdx.x) >> 5;
    int lane = threadIdx.x & 31;
    if (warp >= B) return;
    const float* row = emb + (size_t)warp * DDIM;
    float x[8];
    {
        float4 a = *reinterpret_cast<const float4*>(row + lane * 8);
        float4 b = *reinterpret_cast<const float4*>(row + lane * 8 + 4);
        x[0]=a.x; x[1]=a.y; x[2]=a.z; x[3]=a.w; x[4]=b.x; x[5]=b.y; x[6]=b.z; x[7]=b.w;
    }
    float s = 0.f;
    unsigned hu[4];
#pragma unroll
    for (int e = 0; e < 8; e += 2) {
        __nv_bfloat16 h0 = __float2bfloat16(x[e]);
        __nv_bfloat16 h1 = __float2bfloat16(x[e + 1]);
        hu[e >> 1] = (unsigned)__bfloat16_as_ushort(h0) | ((unsigned)__bfloat16_as_ushort(h1) << 16);
        s = fmaf(x[e], x[e], s);
        s = fmaf(x[e + 1], x[e + 1], s);
    }
    g_ehi4[warp * 32 + lane] = make_uint4(hu[0], hu[1], hu[2], hu[3]);
#pragma unroll
    for (int off = 16; off; off >>= 1) s += __shfl_xor_sync(0xffffffffu, s, off);
    if (lane == 0) {
        g_basec[warp] = -10.0f * s;
        int lab = g_lab64 ? (int)((const long long*)labels)[warp]
                          : ((const int*)labels)[warp];
        g_lab[warp] = lab;
    }
}

// ------------- class bucketing -------------
__global__ void sortclass_kernel() {
    __shared__ int h[256], off[256];
    int t = threadIdx.x;
    h[t] = 0;
    __syncthreads();
    for (int i = t; i < B; i += 256) atomicAdd(&h[g_lab[i] & 255], 1);
    __syncthreads();
    if (t == 0) {
        int acc = 0;
        for (int c = 0; c < 256; ++c) { off[c] = acc; acc += h[c]; }
    }
    __syncthreads();
    g_cnt[t] = h[t];
    g_off[t] = off[t];
    h[t] = off[t];
    __syncthreads();
    for (int i = t; i < B; i += 256) {
        int pos = atomicAdd(&h[g_lab[i] & 255], 1);
        g_cls[pos] = i;
    }
}

// ------- threefry2x32, JAX partitionable mode, key=(0,42) ------------------
__device__ __forceinline__ unsigned rotl32(unsigned x, int r) {
    return __funnelshift_l(x, x, r);
}
__device__ __forceinline__ unsigned threefry_bits(unsigned idx) {
    const unsigned ks0 = 0u, ks1 = 42u, ks2 = 0u ^ 42u ^ 0x1BD11BDAu;
    unsigned x0 = 0u + ks0, x1 = idx + ks1;
#define TFR(r) { x0 += x1; x1 = rotl32(x1, r); x1 ^= x0; }
    TFR(13) TFR(15) TFR(26) TFR(6)   x0 += ks1; x1 += ks2 + 1u;
    TFR(17) TFR(29) TFR(16) TFR(24)  x0 += ks2; x1 += ks0 + 2u;
    TFR(13) TFR(15) TFR(26) TFR(6)   x0 += ks0; x1 += ks1 + 3u;
    TFR(17) TFR(29) TFR(16) TFR(24)  x0 += ks1; x1 += ks2 + 4u;
    TFR(13) TFR(15) TFR(26) TFR(6)   x0 += ks2; x1 += ks0 + 5u;
#undef TFR
    return x0 ^ x1;
}

// ------------- positive selection: warp per row over its class list --------
__global__ void select_kernel() {
    int warp = (blockIdx.x * blockDim.x + threadIdx.x) >> 5;
    int lane = threadIdx.x & 31;
    if (warp >= B) return;
    int i = warp;
    int lab = g_lab[i] & 255;
    int base = g_off[lab], n = g_cnt[lab];
    unsigned bv = 0; int bj = -1;
    for (int t = lane; t < n; t += 32) {
        int j = g_cls[base + t];
        if (j == i) continue;
        unsigned v = threefry_bits((unsigned)(i * B + j)) >> 9;
        if (bj < 0 || v > bv || (v == bv && j < bj)) { bv = v; bj = j; }
    }
    const unsigned full = 0xffffffffu;
#pragma unroll
    for (int off = 16; off; off >>= 1) {
        unsigned ov = __shfl_down_sync(full, bv, off);
        int oj = __shfl_down_sync(full, bj, off);
        if (oj >= 0 && (bj < 0 || ov > bv || (ov == bv && oj < bj))) { bv = ov; bj = oj; }
    }
    if (lane == 0) {
        g_jsel[i] = bj;
        g_valid[i] = (n - 1 > 0) && (B - n > 0);
    }
}

// ------------- exact fp32 numerator: one dot per row -----------------------
__global__ void num_kernel(const float* __restrict__ emb) {
    int warp = (blockIdx.x * blockDim.x + threadIdx.x) >> 5;
    int lane = threadIdx.x & 31;
    if (warp >= B) return;
    int j = g_jsel[warp];
    if (j < 0) { if (lane == 0) g_num[warp] = 0.f; return; }
    const float* xi = emb + (size_t)warp * DDIM;
    const float* xj = emb + (size_t)j * DDIM;
    float g = 0.f;
#pragma unroll
    for (int k = 0; k < 8; k += 4) {
        float4 a = *reinterpret_cast<const float4*>(xi + lane * 8 + k);
        float4 b = *reinterpret_cast<const float4*>(xj + lane * 8 + k);
        g = fmaf(a.x, b.x, g); g = fmaf(a.y, b.y, g);
        g = fmaf(a.z, b.z, g); g = fmaf(a.w, b.w, g);
    }
#pragma unroll
    for (int off = 16; off; off >>= 1) g += __shfl_xor_sync(0xffffffffu, g, off);
    if (lane == 0)
        g_num[warp] = fminf(fmaf(20.f, g, g_basec[warp] + g_basec[j]), 0.f);
}

// ------------- main: bf16 HMMA Gram (A in regs) + fused logsumexp ----------
__device__ __forceinline__ void stage_tile(int c0, int p, int tid, uint32_t smb) {
    uint32_t bbuf = smb + SM_B0 + (uint32_t)p * 32768u;
#pragma unroll
    for (int it = 0; it < 16; ++it) {
        int f = tid + it * THREADS;
        int n = f >> 5, v = f & 31;
        uint32_t off = (uint32_t)(n * 512 + v * 16);
        off ^= (uint32_t)(n & 7) << 4;
        cpa16(bbuf + off, g_ehi4 + (size_t)(c0 + n) * 32 + v);
    }
    uint32_t mbuf = smb + SM_META + (uint32_t)p * 512u;
    if (tid < 16)      cpa16(mbuf + tid * 16, (const char*)g_basec + (size_t)c0 * 4 + tid * 16);
    else if (tid < 32) cpa16(mbuf + 256 + (tid - 16) * 16, (const char*)g_lab + (size_t)c0 * 4 + (tid - 16) * 16);
    cp_commit();
}

__global__ void __launch_bounds__(THREADS, 2)
main_kernel() {
    extern __shared__ char smem[];
    const uint32_t smb = smem_u32(smem);
    const int tid = threadIdx.x;
    const int lane = tid & 31, wid = tid >> 5;
    const int wm = wid >> 1, wn = wid & 1;      // 2x2 warp grid, warp tile 32x32
    const int rowBase = blockIdx.y * BM;
    const int colBase = blockIdx.x * COLS_PER_CTA;
    const int split = blockIdx.x;

    // prologue: kick off tile 0, stage A to smem
    stage_tile(colBase, 0, tid, smb);
#pragma unroll
    for (int it = 0; it < 16; ++it) {
        int f = tid + it * THREADS;
        int m = f >> 5, v = f & 31;
        uint4 val = g_ehi4[(size_t)(rowBase + m) * 32 + v];
        uint32_t off = (uint32_t)(m * 512 + v * 16);
        off ^= (uint32_t)(m & 7) << 4;
        *(uint4*)(smem + SM_A + off) = val;
    }
    __syncthreads();

    // hoist ALL A fragments into registers (reused for all 64 col tiles)
    const int arow = wm * 32 + (lane & 15);
    const uint32_t aswz = (uint32_t)(lane & 7) << 4;
    const uint32_t aoff0 = (uint32_t)(arow * 512 + ((lane >> 4) * 16));
    uint32_t areg[KSTEPS][2][4];
#pragma unroll
    for (int ks = 0; ks < KSTEPS; ++ks)
#pragma unroll
        for (int mf = 0; mf < 2; ++mf) {
            uint32_t off = (aoff0 + (uint32_t)(mf * 8192 + ks * 32)) ^ aswz;
            ldsm4(areg[ks][mf][0], areg[ks][mf][1], areg[ks][mf][2], areg[ks][mf][3],
                  smb + SM_A + off);
        }

    // per-thread row metadata (4 rows within warp-m tile); lm in shifted domain
    float bi[4]; int labi[4];
    float lm[4], ls[4];
#pragma unroll
    for (int r = 0; r < 4; ++r) {
        int rloc = wm * 32 + (lane >> 2) + (r & 1) * 8 + (r >> 1) * 16;
        int rg = rowBase + rloc;
        bi[r]   = g_basec[rg];
        labi[r] = g_lab[rg];
        lm[r] = -1e30f; ls[r] = 0.f;
    }

    const int brow = ((lane >> 4) << 3) + (lane & 7);
    const uint32_t boff0 = (uint32_t)((wn * 32 + brow) * 512 + (((lane >> 3) & 1) * 16));
    const int cq = 2 * (lane & 3);

    for (int ct = 0; ct < NT; ++ct) {
        int p = ct & 1;
        if (ct + 1 < NT) { stage_tile(colBase + (ct + 1) * BN, p ^ 1, tid, smb); cp_wait<1>(); }
        else             { cp_wait<0>(); }
        __syncthreads();

        uint32_t bbuf = smb + SM_B0 + (uint32_t)p * 32768u;
        float acc[2][4][4];
#pragma unroll
        for (int mf = 0; mf < 2; ++mf)
#pragma unroll
            for (int nf = 0; nf < 4; ++nf)
#pragma unroll
                for (int e = 0; e < 4; ++e) acc[mf][nf][e] = 0.f;

#pragma unroll
        for (int ks = 0; ks < KSTEPS; ++ks) {
            uint32_t b[4][2];
#pragma unroll
            for (int nf2 = 0; nf2 < 2; ++nf2) {
                uint32_t off = (boff0 + (uint32_t)(nf2 * 8192 + ks * 32)) ^ aswz;
                uint32_t t0, t1, t2, t3;
                ldsm4(t0, t1, t2, t3, bbuf + off);
                b[nf2 * 2][0] = t0; b[nf2 * 2][1] = t1;
                b[nf2 * 2 + 1][0] = t2; b[nf2 * 2 + 1][1] = t3;
            }
#pragma unroll
            for (int mf = 0; mf < 2; ++mf)
#pragma unroll
                for (int nf = 0; nf < 4; ++nf)
                    mma16816(acc[mf][nf], areg[ks][mf], b[nf]);
        }

        // fused epilogue (shifted domain: sim' = 20*g + mBase[cl] = sim - bi)
        const float* mBase = (const float*)(smem + SM_META + p * 512);
        const int*   mLab  = (const int*)(smem + SM_META + p * 512 + 256);
#pragma unroll
        for (int r = 0; r < 4; ++r) {
            int mf = r >> 1, hh = r & 1;
#pragma unroll
            for (int nf = 0; nf < 4; ++nf) {
#pragma unroll
                for (int e = 0; e < 2; ++e) {
                    int cl = wn * 32 + nf * 8 + cq + e;
                    float sim = fmaf(20.f, acc[mf][nf][hh * 2 + e], mBase[cl]);
                    float d = sim - lm[r];
                    if (d > -87.f && mLab[cl] != labi[r]) {
                        if (d > 0.f) { ls[r] = fmaf(ls[r], __expf(-d), 1.f); lm[r] = sim; }
                        else ls[r] += __expf(d);
                    }
                }
            }
        }
        __syncthreads();   // everyone done with buf p before it is re-staged
    }

    // reduce across the quad (lanes sharing the same rows)
#pragma unroll
    for (int r = 0; r < 4; ++r) {
#pragma unroll
        for (int off = 1; off <= 2; off <<= 1) {
            float mo = __shfl_xor_sync(0xffffffffu, lm[r], off);
            float so = __shfl_xor_sync(0xffffffffu, ls[r], off);
            float mn = fmaxf(lm[r], mo);
            ls[r] = ls[r] * __expf(lm[r] - mn) + so * __expf(mo - mn);
            lm[r] = mn;
        }
    }
    // reduce across the 2 n-warps (un-shift by +bi at write)
    float2* red = (float2*)(smem + SM_RED);
    if ((lane & 3) == 0) {
#pragma unroll
        for (int r = 0; r < 4; ++r) {
            int rloc = wm * 32 + (lane >> 2) + (r & 1) * 8 + (r >> 1) * 16;
            red[wn * 64 + rloc] = make_float2(lm[r] + bi[r], ls[r]);
        }
    }
    __syncthreads();
    if (tid < 64) {
        float2 v0 = red[tid], v1 = red[64 + tid];
        float m = fmaxf(v0.x, v1.x);
        float s = v0.y * __expf(v0.x - m) + v1.y * __expf(v1.x - m);
        g_pm[split][rowBase + tid] = m;
        g_ps[split][rowBase + tid] = s;
    }
}

// ---------------- finalize: combine splits, masked mean --------------------
__global__ void finalize_kernel(float* __restrict__ out) {
    __shared__ double ssum[256];
    __shared__ int    scnt[256];
    int tid = threadIdx.x;
    double acc = 0.0; int cnt = 0;
    for (int r = tid; r < B; r += 256) {
        if (g_valid[r]) {
            float m0 = g_pm[0][r], m1 = g_pm[1][r];
            float m = fmaxf(m0, m1);
            float s = g_ps[0][r] * __expf(m0 - m) + g_ps[1][r] * __expf(m1 - m);
            float denom = m + __logf(s);
            acc += (double)(denom - g_num[r]);
            cnt++;
        }
    }
    ssum[tid] = acc; scnt[tid] = cnt;
    __syncthreads();
    for (int off = 128; off; off >>= 1) {
        if (tid < off) { ssum[tid] += ssum[tid + off]; scnt[tid] += scnt[tid + off]; }
        __syncthreads();
    }
    if (tid == 0)
        out[0] = (scnt[0] > 0) ? (float)(ssum[0] / (double)scnt[0]) : 0.0f;
}

// ---------------------------------------------------------------------------
extern "C" void kernel_launch(void* const* d_in, const int* in_sizes, int n_in,
                              void* d_out, int out_size) {
    const float* emb    = (const float*)d_in[0];
    const void*  labels = d_in[1];

    cudaFuncSetAttribute(main_kernel,
                         cudaFuncAttributeMaxDynamicSharedMemorySize, SM_TOTAL);

    detect_kernel<<<1, 256>>>((const unsigned*)labels);
    prep_kernel<<<B / 8, 256>>>(emb, labels);
    sortclass_kernel<<<1, 256>>>();
    select_kernel<<<B / 8, 256>>>();
    num_kernel<<<B / 8, 256>>>(emb);
    main_kernel<<<dim3(COLSPLIT, B / BM), THREADS, SM_TOTAL>>>();
    finalize_kernel<<<1, 256>>>((float*)d_out);
}

// round 14
// speedup vs baseline: 7.9668x; 1.5144x over previous
#include <cuda_runtime.h>
#include <cuda_bf16.h>
#include <cstdint>

#define B     8192
#define DDIM  256
#define BM    64
#define BN    64
#define COLSPLIT 2
#define COLS_PER_CTA (B / COLSPLIT)   // 4096
#define NT    (COLS_PER_CTA / BN)     // 64 col tiles
#define KSTEPS 16                     // K = 256, pure bf16 hi
#define THREADS 128
#define K2E   28.853900817779268f     // 20 * log2(e)
#define LN2   0.6931471805599453f
#define MASKV (-1e38f)
// SMEM layout (bytes)
#define SM_A    0                     // 64 rows * 512 B = 32768
#define SM_B0   32768                 // 64 * 512 B = 32768
#define SM_B1   65536
#define SM_META 98304                 // 2 * (64 f32 base2 + 64 i32 lab) = 1024
#define SM_RED  99328                 // 2 * 64 * float2 = 1024
#define SM_TOTAL 100352

// ---------------- scratch ----------------
__device__ uint4 g_ehi4[B * DDIM / 8];
__device__ float g_basec[B];      // -10*||x||^2            (ln domain, numerator)
__device__ float g_basel2[B];     // -10*log2(e)*||x||^2    (log2 domain, lse)
__device__ int   g_lab[B];
__device__ int   g_jsel[B];
__device__ int   g_valid[B];
__device__ float g_num[B];
__device__ float g_pm[COLSPLIT][B];   // log2-domain max
__device__ float g_ps[COLSPLIT][B];   // log2-domain sum
__device__ int   g_lab64;
__device__ int   g_off[256];
__device__ int   g_cnt[256];
__device__ int   g_cls[B];

// ---------------- helpers ----------------
__device__ __forceinline__ uint32_t smem_u32(const void* p) {
    uint32_t a;
    asm("{ .reg .u64 t; cvta.to.shared.u64 t, %1; cvt.u32.u64 %0, t; }" : "=r"(a) : "l"(p));
    return a;
}
__device__ __forceinline__ float ex2(float x) {
    float y;
    asm("ex2.approx.ftz.f32 %0, %1;" : "=f"(y) : "f"(x));
    return y;
}
__device__ __forceinline__ void cpa16(uint32_t dst, const void* src) {
    asm volatile("cp.async.cg.shared.global [%0], [%1], 16;" :: "r"(dst), "l"(src));
}
__device__ __forceinline__ void cp_commit() { asm volatile("cp.async.commit_group;" ::: "memory"); }
template<int N> __device__ __forceinline__ void cp_wait() {
    asm volatile("cp.async.wait_group %0;" :: "n"(N) : "memory");
}
__device__ __forceinline__ void ldsm4(uint32_t& r0, uint32_t& r1, uint32_t& r2, uint32_t& r3, uint32_t a) {
    asm volatile("ldmatrix.sync.aligned.m8n8.x4.shared.b16 {%0,%1,%2,%3}, [%4];"
                 : "=r"(r0), "=r"(r1), "=r"(r2), "=r"(r3) : "r"(a));
}
__device__ __forceinline__ void mma16816(float* d, const uint32_t* a, const uint32_t* b) {
    asm volatile("mma.sync.aligned.m16n8k16.row.col.f32.bf16.bf16.f32 "
                 "{%0,%1,%2,%3}, {%4,%5,%6,%7}, {%8,%9}, {%0,%1,%2,%3};"
                 : "+f"(d[0]), "+f"(d[1]), "+f"(d[2]), "+f"(d[3])
                 : "r"(a[0]), "r"(a[1]), "r"(a[2]), "r"(a[3]), "r"(b[0]), "r"(b[1]));
}

// ------------- dtype detect: odd 32-bit words all zero <=> int64 ----------
__global__ void detect_kernel(const unsigned* __restrict__ words) {
    __shared__ unsigned sOr[256];
    unsigned v = 0;
    for (int k = threadIdx.x; k < B / 2; k += 256) v |= words[2 * k + 1];
    sOr[threadIdx.x] = v;
    __syncthreads();
    for (int off = 128; off; off >>= 1) {
        if (threadIdx.x < off) sOr[threadIdx.x] |= sOr[threadIdx.x + off];
        __syncthreads();
    }
    if (threadIdx.x == 0) g_lab64 = (sOr[0] == 0u) ? 1 : 0;
}

// ------------- prep: norms, labels, bf16 convert ---------------------------
__global__ void prep_kernel(const float* __restrict__ emb,
                            const void* __restrict__ labels) {
    int warp = (blockIdx.x * blockDim.x + threadIdx.x) >> 5;
    int lane = threadIdx.x & 31;
    if (warp >= B) return;
    const float* row = emb + (size_t)warp * DDIM;
    float x[8];
    {
        float4 a = *reinterpret_cast<const float4*>(row + lane * 8);
        float4 b = *reinterpret_cast<const float4*>(row + lane * 8 + 4);
        x[0]=a.x; x[1]=a.y; x[2]=a.z; x[3]=a.w; x[4]=b.x; x[5]=b.y; x[6]=b.z; x[7]=b.w;
    }
    float s = 0.f;
    unsigned hu[4];
#pragma unroll
    for (int e = 0; e < 8; e += 2) {
        __nv_bfloat16 h0 = __float2bfloat16(x[e]);
        __nv_bfloat16 h1 = __float2bfloat16(x[e + 1]);
        hu[e >> 1] = (unsigned)__bfloat16_as_ushort(h0) | ((unsigned)__bfloat16_as_ushort(h1) << 16);
        s = fmaf(x[e], x[e], s);
        s = fmaf(x[e + 1], x[e + 1], s);
    }
    g_ehi4[warp * 32 + lane] = make_uint4(hu[0], hu[1], hu[2], hu[3]);
#pragma unroll
    for (int off = 16; off; off >>= 1) s += __shfl_xor_sync(0xffffffffu, s, off);
    if (lane == 0) {
        g_basec[warp]  = -10.0f * s;
        g_basel2[warp] = -10.0f * 1.4426950408889634f * s;
        int lab = g_lab64 ? (int)((const long long*)labels)[warp]
                          : ((const int*)labels)[warp];
        g_lab[warp] = lab;
    }
}

// ------------- class bucketing -------------
__global__ void sortclass_kernel() {
    __shared__ int h[256], off[256];
    int t = threadIdx.x;
    h[t] = 0;
    __syncthreads();
    for (int i = t; i < B; i += 256) atomicAdd(&h[g_lab[i] & 255], 1);
    __syncthreads();
    if (t == 0) {
        int acc = 0;
        for (int c = 0; c < 256; ++c) { off[c] = acc; acc += h[c]; }
    }
    __syncthreads();
    g_cnt[t] = h[t];
    g_off[t] = off[t];
    h[t] = off[t];
    __syncthreads();
    for (int i = t; i < B; i += 256) {
        int pos = atomicAdd(&h[g_lab[i] & 255], 1);
        g_cls[pos] = i;
    }
}

// ------- threefry2x32, JAX partitionable mode, key=(0,42) ------------------
__device__ __forceinline__ unsigned rotl32(unsigned x, int r) {
    return __funnelshift_l(x, x, r);
}
__device__ __forceinline__ unsigned threefry_bits(unsigned idx) {
    const unsigned ks0 = 0u, ks1 = 42u, ks2 = 0u ^ 42u ^ 0x1BD11BDAu;
    unsigned x0 = 0u + ks0, x1 = idx + ks1;
#define TFR(r) { x0 += x1; x1 = rotl32(x1, r); x1 ^= x0; }
    TFR(13) TFR(15) TFR(26) TFR(6)   x0 += ks1; x1 += ks2 + 1u;
    TFR(17) TFR(29) TFR(16) TFR(24)  x0 += ks2; x1 += ks0 + 2u;
    TFR(13) TFR(15) TFR(26) TFR(6)   x0 += ks0; x1 += ks1 + 3u;
    TFR(17) TFR(29) TFR(16) TFR(24)  x0 += ks1; x1 += ks2 + 4u;
    TFR(13) TFR(15) TFR(26) TFR(6)   x0 += ks2; x1 += ks0 + 5u;
#undef TFR
    return x0 ^ x1;
}

// ------------- positive selection: warp per row over its class list --------
__global__ void select_kernel() {
    int warp = (blockIdx.x * blockDim.x + threadIdx.x) >> 5;
    int lane = threadIdx.x & 31;
    if (warp >= B) return;
    int i = warp;
    int lab = g_lab[i] & 255;
    int base = g_off[lab], n = g_cnt[lab];
    unsigned bv = 0; int bj = -1;
    for (int t = lane; t < n; t += 32) {
        int j = g_cls[base + t];
        if (j == i) continue;
        unsigned v = threefry_bits((unsigned)(i * B + j)) >> 9;
        if (bj < 0 || v > bv || (v == bv && j < bj)) { bv = v; bj = j; }
    }
    const unsigned full = 0xffffffffu;
#pragma unroll
    for (int off = 16; off; off >>= 1) {
        unsigned ov = __shfl_down_sync(full, bv, off);
        int oj = __shfl_down_sync(full, bj, off);
        if (oj >= 0 && (bj < 0 || ov > bv || (ov == bv && oj < bj))) { bv = ov; bj = oj; }
    }
    if (lane == 0) {
        g_jsel[i] = bj;
        g_valid[i] = (n - 1 > 0) && (B - n > 0);
    }
}

// ------------- exact fp32 numerator: one dot per row -----------------------
__global__ void num_kernel(const float* __restrict__ emb) {
    int warp = (blockIdx.x * blockDim.x + threadIdx.x) >> 5;
    int lane = threadIdx.x & 31;
    if (warp >= B) return;
    int j = g_jsel[warp];
    if (j < 0) { if (lane == 0) g_num[warp] = 0.f; return; }
    const float* xi = emb + (size_t)warp * DDIM;
    const float* xj = emb + (size_t)j * DDIM;
    float g = 0.f;
#pragma unroll
    for (int k = 0; k < 8; k += 4) {
        float4 a = *reinterpret_cast<const float4*>(xi + lane * 8 + k);
        float4 b = *reinterpret_cast<const float4*>(xj + lane * 8 + k);
        g = fmaf(a.x, b.x, g); g = fmaf(a.y, b.y, g);
        g = fmaf(a.z, b.z, g); g = fmaf(a.w, b.w, g);
    }
#pragma unroll
    for (int off = 16; off; off >>= 1) g += __shfl_xor_sync(0xffffffffu, g, off);
    if (lane == 0)
        g_num[warp] = fminf(fmaf(20.f, g, g_basec[warp] + g_basec[j]), 0.f);
}

// ------------- main: bf16 HMMA Gram (A in regs) + branchless lse -----------
__device__ __forceinline__ void stage_tile(int c0, int p, int tid, uint32_t smb) {
    uint32_t bbuf = smb + SM_B0 + (uint32_t)p * 32768u;
#pragma unroll
    for (int it = 0; it < 16; ++it) {
        int f = tid + it * THREADS;
        int n = f >> 5, v = f & 31;
        uint32_t off = (uint32_t)(n * 512 + v * 16);
        off ^= (uint32_t)(n & 7) << 4;
        cpa16(bbuf + off, g_ehi4 + (size_t)(c0 + n) * 32 + v);
    }
    uint32_t mbuf = smb + SM_META + (uint32_t)p * 512u;
    if (tid < 16)      cpa16(mbuf + tid * 16, (const char*)g_basel2 + (size_t)c0 * 4 + tid * 16);
    else if (tid < 32) cpa16(mbuf + 256 + (tid - 16) * 16, (const char*)g_lab + (size_t)c0 * 4 + (tid - 16) * 16);
    cp_commit();
}

__global__ void __launch_bounds__(THREADS, 2)
main_kernel() {
    extern __shared__ char smem[];
    const uint32_t smb = smem_u32(smem);
    const int tid = threadIdx.x;
    const int lane = tid & 31, wid = tid >> 5;
    const int wm = wid >> 1, wn = wid & 1;      // 2x2 warp grid, warp tile 32x32
    const int rowBase = blockIdx.y * BM;
    const int colBase = blockIdx.x * COLS_PER_CTA;
    const int split = blockIdx.x;

    // prologue: kick off tile 0, stage A to smem
    stage_tile(colBase, 0, tid, smb);
#pragma unroll
    for (int it = 0; it < 16; ++it) {
        int f = tid + it * THREADS;
        int m = f >> 5, v = f & 31;
        uint4 val = g_ehi4[(size_t)(rowBase + m) * 32 + v];
        uint32_t off = (uint32_t)(m * 512 + v * 16);
        off ^= (uint32_t)(m & 7) << 4;
        *(uint4*)(smem + SM_A + off) = val;
    }
    __syncthreads();

    // hoist ALL A fragments into registers (reused for all 64 col tiles)
    const int arow = wm * 32 + (lane & 15);
    const uint32_t aswz = (uint32_t)(lane & 7) << 4;
    const uint32_t aoff0 = (uint32_t)(arow * 512 + ((lane >> 4) * 16));
    uint32_t areg[KSTEPS][2][4];
#pragma unroll
    for (int ks = 0; ks < KSTEPS; ++ks)
#pragma unroll
        for (int mf = 0; mf < 2; ++mf) {
            uint32_t off = (aoff0 + (uint32_t)(mf * 8192 + ks * 32)) ^ aswz;
            ldsm4(areg[ks][mf][0], areg[ks][mf][1], areg[ks][mf][2], areg[ks][mf][3],
                  smb + SM_A + off);
        }

    // per-thread row metadata; (lm, ls) in shifted log2 domain
    float bi2[4]; int labi[4];
    float lm[4], ls[4];
#pragma unroll
    for (int r = 0; r < 4; ++r) {
        int rloc = wm * 32 + (lane >> 2) + (r & 1) * 8 + (r >> 1) * 16;
        int rg = rowBase + rloc;
        bi2[r]  = g_basel2[rg];
        labi[r] = g_lab[rg];
        lm[r] = MASKV; ls[r] = 0.f;
    }

    const int brow = ((lane >> 4) << 3) + (lane & 7);
    const uint32_t boff0 = (uint32_t)((wn * 32 + brow) * 512 + (((lane >> 3) & 1) * 16));
    const int cq = 2 * (lane & 3);

    for (int ct = 0; ct < NT; ++ct) {
        int p = ct & 1;
        if (ct + 1 < NT) { stage_tile(colBase + (ct + 1) * BN, p ^ 1, tid, smb); cp_wait<1>(); }
        else             { cp_wait<0>(); }
        __syncthreads();

        uint32_t bbuf = smb + SM_B0 + (uint32_t)p * 32768u;
        float acc[2][4][4];
#pragma unroll
        for (int mf = 0; mf < 2; ++mf)
#pragma unroll
            for (int nf = 0; nf < 4; ++nf)
#pragma unroll
                for (int e = 0; e < 4; ++e) acc[mf][nf][e] = 0.f;

#pragma unroll
        for (int ks = 0; ks < KSTEPS; ++ks) {
            uint32_t b[4][2];
#pragma unroll
            for (int nf2 = 0; nf2 < 2; ++nf2) {
                uint32_t off = (boff0 + (uint32_t)(nf2 * 8192 + ks * 32)) ^ aswz;
                uint32_t t0, t1, t2, t3;
                ldsm4(t0, t1, t2, t3, bbuf + off);
                b[nf2 * 2][0] = t0; b[nf2 * 2][1] = t1;
                b[nf2 * 2 + 1][0] = t2; b[nf2 * 2 + 1][1] = t3;
            }
#pragma unroll
            for (int mf = 0; mf < 2; ++mf)
#pragma unroll
                for (int nf = 0; nf < 4; ++nf)
                    mma16816(acc[mf][nf], areg[ks][mf], b[nf]);
        }

        // branchless epilogue in shifted log2 domain
        const float* mBase = (const float*)(smem + SM_META + p * 512);
        const int*   mLab  = (const int*)(smem + SM_META + p * 512 + 256);
        float cb[8]; int clb[8];
#pragma unroll
        for (int j = 0; j < 8; ++j) {
            int cl = wn * 32 + (j >> 1) * 8 + cq + (j & 1);
            cb[j] = mBase[cl];
            clb[j] = mLab[cl];
        }
#pragma unroll
        for (int r = 0; r < 4; ++r) {
            int mf = r >> 1, hh = r & 1;
            float sv[8];
#pragma unroll
            for (int j = 0; j < 8; ++j) {
                float s2 = fmaf(K2E, acc[mf][j >> 1][hh * 2 + (j & 1)], cb[j]);
                sv[j] = (clb[j] != labi[r]) ? s2 : MASKV;
            }
            float t0 = fmaxf(sv[0], sv[1]), t1 = fmaxf(sv[2], sv[3]);
            float t2 = fmaxf(sv[4], sv[5]), t3 = fmaxf(sv[6], sv[7]);
            float tmax = fmaxf(fmaxf(t0, t1), fmaxf(t2, t3));
            float mnew = fmaxf(lm[r], tmax);
            float a0 = ex2(sv[0] - mnew) + ex2(sv[1] - mnew);
            float a1 = ex2(sv[2] - mnew) + ex2(sv[3] - mnew);
            float a2 = ex2(sv[4] - mnew) + ex2(sv[5] - mnew);
            float a3 = ex2(sv[6] - mnew) + ex2(sv[7] - mnew);
            float asum = (a0 + a1) + (a2 + a3);
            ls[r] = fmaf(ls[r], ex2(lm[r] - mnew), asum);
            lm[r] = mnew;
        }
        __syncthreads();   // everyone done with buf p before it is re-staged
    }

    // reduce across the quad (lanes sharing the same rows) — log2 domain
#pragma unroll
    for (int r = 0; r < 4; ++r) {
#pragma unroll
        for (int off = 1; off <= 2; off <<= 1) {
            float mo = __shfl_xor_sync(0xffffffffu, lm[r], off);
            float so = __shfl_xor_sync(0xffffffffu, ls[r], off);
            float mn = fmaxf(lm[r], mo);
            ls[r] = ls[r] * ex2(lm[r] - mn) + so * ex2(mo - mn);
            lm[r] = mn;
        }
    }
    // reduce across the 2 n-warps (un-shift by +bi2 at write)
    float2* red = (float2*)(smem + SM_RED);
    if ((lane & 3) == 0) {
#pragma unroll
        for (int r = 0; r < 4; ++r) {
            int rloc = wm * 32 + (lane >> 2) + (r & 1) * 8 + (r >> 1) * 16;
            red[wn * 64 + rloc] = make_float2(lm[r] + bi2[r], ls[r]);
        }
    }
    __syncthreads();
    if (tid < 64) {
        float2 v0 = red[tid], v1 = red[64 + tid];
        float m = fmaxf(v0.x, v1.x);
        float s = v0.y * ex2(v0.x - m) + v1.y * ex2(v1.x - m);
        g_pm[split][rowBase + tid] = m;
        g_ps[split][rowBase + tid] = s;
    }
}

// ---------------- finalize: combine splits (log2), masked mean -------------
__global__ void finalize_kernel(float* __restrict__ out) {
    __shared__ double ssum[256];
    __shared__ int    scnt[256];
    int tid = threadIdx.x;
    double acc = 0.0; int cnt = 0;
    for (int r = tid; r < B; r += 256) {
        if (g_valid[r]) {
            float m0 = g_pm[0][r], m1 = g_pm[1][r];
            float m = fmaxf(m0, m1);
            float s = g_ps[0][r] * ex2(m0 - m) + g_ps[1][r] * ex2(m1 - m);
            float denom = (m + __log2f(s)) * LN2;   // back to ln domain
            acc += (double)(denom - g_num[r]);
            cnt++;
        }
    }
    ssum[tid] = acc; scnt[tid] = cnt;
    __syncthreads();
    for (int off = 128; off; off >>= 1) {
        if (tid < off) { ssum[tid] += ssum[tid + off]; scnt[tid] += scnt[tid + off]; }
        __syncthreads();
    }
    if (tid == 0)
        out[0] = (scnt[0] > 0) ? (float)(ssum[0] / (double)scnt[0]) : 0.0f;
}

// ---------------------------------------------------------------------------
extern "C" void kernel_launch(void* const* d_in, const int* in_sizes, int n_in,
                              void* d_out, int out_size) {
    const float* emb    = (const float*)d_in[0];
    const void*  labels = d_in[1];

    cudaFuncSetAttribute(main_kernel,
                         cudaFuncAttributeMaxDynamicSharedMemorySize, SM_TOTAL);

    detect_kernel<<<1, 256>>>((const unsigned*)labels);
    prep_kernel<<<B / 8, 256>>>(emb, labels);
    sortclass_kernel<<<1, 256>>>();
    select_kernel<<<B / 8, 256>>>();
    num_kernel<<<B / 8, 256>>>(emb);
    main_kernel<<<dim3(COLSPLIT, B / BM), THREADS, SM_TOTAL>>>();
    finalize_kernel<<<1, 256>>>((float*)d_out);
}